// round 2
// baseline (speedup 1.0000x reference)
#include <cuda_runtime.h>
#include <cstdint>
#include <cstddef>

#define H 16
#define DMODEL 1024
#define DK 64
#define BB 2
#define SS 2048
#define M_ROWS (BB*SS)   // 4096

// Scratch (device globals — no allocation allowed)
__device__ float g_q[(size_t)BB*H*SS*DK];
__device__ float g_k[(size_t)BB*H*SS*DK];
__device__ float g_v[(size_t)BB*H*SS*DK];
__device__ float g_attn[(size_t)BB*SS*DMODEL];

// ---------------------------------------------------------------------------
// SGEMM: C = A[M,K] @ W[N,K]^T + bias[N]
// LAYOUT 0: C row-major [M,N]
// LAYOUT 1: C scattered to head-major [b,h,s,dk] (for Q/K/V projections)
// ---------------------------------------------------------------------------
#define BM 128
#define BN 128
#define BK 16

template<int LAYOUT>
__global__ __launch_bounds__(256)
void gemm_nt(const float* __restrict__ A, const float* __restrict__ W,
             const float* __restrict__ bias, float* __restrict__ C,
             int M, int N, int K)
{
    __shared__ float As[BK][BM + 4];
    __shared__ float Bs[BK][BN + 4];

    const int tid = threadIdx.x;
    const int tx = tid & 15;
    const int ty = tid >> 4;
    const int m0 = blockIdx.y * BM;
    const int n0 = blockIdx.x * BN;

    float acc[8][8];
    #pragma unroll
    for (int i = 0; i < 8; i++)
        #pragma unroll
        for (int j = 0; j < 8; j++) acc[i][j] = 0.f;

    for (int k0 = 0; k0 < K; k0 += BK) {
        // Load A tile [128 x 16] and W tile [128 x 16], transposed into smem
        #pragma unroll
        for (int it = 0; it < 2; it++) {
            int idx = tid + it * 256;           // 0..511
            int row = idx >> 2;                 // 0..127
            int kc  = (idx & 3) << 2;           // 0,4,8,12
            float4 av = *(const float4*)&A[(size_t)(m0 + row) * K + k0 + kc];
            As[kc + 0][row] = av.x; As[kc + 1][row] = av.y;
            As[kc + 2][row] = av.z; As[kc + 3][row] = av.w;
            float4 bv = *(const float4*)&W[(size_t)(n0 + row) * K + k0 + kc];
            Bs[kc + 0][row] = bv.x; Bs[kc + 1][row] = bv.y;
            Bs[kc + 2][row] = bv.z; Bs[kc + 3][row] = bv.w;
        }
        __syncthreads();

        #pragma unroll
        for (int kk = 0; kk < BK; kk++) {
            float a[8], b[8];
            #pragma unroll
            for (int i = 0; i < 8; i++) a[i] = As[kk][ty * 8 + i];
            #pragma unroll
            for (int j = 0; j < 8; j++) b[j] = Bs[kk][tx * 8 + j];
            #pragma unroll
            for (int i = 0; i < 8; i++)
                #pragma unroll
                for (int j = 0; j < 8; j++) acc[i][j] += a[i] * b[j];
        }
        __syncthreads();
    }

    #pragma unroll
    for (int i = 0; i < 8; i++) {
        int m = m0 + ty * 8 + i;
        #pragma unroll
        for (int j = 0; j < 8; j++) {
            int n = n0 + tx * 8 + j;
            float v = acc[i][j] + bias[n];
            if (LAYOUT == 0) {
                C[(size_t)m * N + n] = v;
            } else {
                int b  = m >> 11;       // / SS
                int s  = m & (SS - 1);
                int h  = n >> 6;        // / DK
                int dk = n & (DK - 1);
                C[((((size_t)b * H + h) * SS + s) * DK) + dk] = v;
            }
        }
    }
}

// ---------------------------------------------------------------------------
// Flash-style masked attention.
// One block = 128 q-rows for one (b, h). 128 threads, one q-row per thread.
// Key tile = 32 rows so ALL shared fits statically under 48KB (no
// cudaFuncSetAttribute needed -> nothing unusual in the capture path).
// ---------------------------------------------------------------------------
#define KT 32

__global__ __launch_bounds__(128)
void attn_kernel(const int* __restrict__ mask)
{
    __shared__ float Ks[KT * DK];        // 8 KB
    __shared__ float Vs[KT * DK];        // 8 KB
    __shared__ float Ss[128 * (KT + 1)]; // 16.9 KB, stride 33 = conflict-free

    const int r  = threadIdx.x;         // q-row within block
    const int q0 = blockIdx.x * 128;
    const int h  = blockIdx.y;
    const int b  = blockIdx.z;
    const int qg = q0 + r;

    const float* qptr = g_q + (((size_t)b * H + h) * SS + qg) * DK;
    float4 q4[16];
    #pragma unroll
    for (int d = 0; d < 16; d++) q4[d] = ((const float4*)qptr)[d];

    const float4* kbase = (const float4*)(g_k + (((size_t)b * H + h) * SS) * DK);
    const float4* vbase = (const float4*)(g_v + (((size_t)b * H + h) * SS) * DK);
    const int* mrow_base = mask + ((size_t)b * SS + qg) * SS;

    float4 o4[16];
    #pragma unroll
    for (int d = 0; d < 16; d++) o4[d] = make_float4(0.f, 0.f, 0.f, 0.f);
    float mrun = -1e30f;
    float l = 0.f;

    for (int t = 0; t < SS / KT; t++) {
        const int k0 = t * KT;

        // Cooperative load K/V tiles: 32 rows x 16 float4 = 512 float4 each.
        // 128 threads -> 4 float4 per thread per array.
        #pragma unroll
        for (int it = 0; it < 4; it++) {
            int idx = r + it * 128;
            int j   = idx >> 4;
            int d4  = idx & 15;
            ((float4*)Ks)[j * 16 + d4] = kbase[(size_t)(k0 + j) * 16 + d4];
            ((float4*)Vs)[j * 16 + d4] = vbase[(size_t)(k0 + j) * 16 + d4];
        }
        __syncthreads();

        // Scores for this thread's q-row against KT keys
        const int* mrow = mrow_base + k0;
        float tmax = mrun;
        #pragma unroll 4
        for (int j = 0; j < KT; j++) {
            const float4* kr = (const float4*)(Ks + j * DK);
            float s0 = 0.f, s1 = 0.f, s2 = 0.f, s3 = 0.f;
            #pragma unroll
            for (int d = 0; d < 16; d++) {
                float4 kv = kr[d];
                s0 += q4[d].x * kv.x;
                s1 += q4[d].y * kv.y;
                s2 += q4[d].z * kv.z;
                s3 += q4[d].w * kv.w;
            }
            float s = ((s0 + s1) + (s2 + s3)) * 0.125f;   // 1/sqrt(64)
            if (__ldg(&mrow[j]) == 0) s = -10000.0f;
            Ss[r * (KT + 1) + j] = s;
            tmax = fmaxf(tmax, s);
        }

        // Online-softmax rescale
        float alpha = __expf(mrun - tmax);
        mrun = tmax;
        l *= alpha;
        #pragma unroll
        for (int d = 0; d < 16; d++) {
            o4[d].x *= alpha; o4[d].y *= alpha;
            o4[d].z *= alpha; o4[d].w *= alpha;
        }

        // P @ V accumulate
        #pragma unroll 2
        for (int j = 0; j < KT; j++) {
            float p = __expf(Ss[r * (KT + 1) + j] - tmax);
            l += p;
            const float4* vr = (const float4*)(Vs + j * DK);
            #pragma unroll
            for (int d = 0; d < 16; d++) {
                float4 vv = vr[d];
                o4[d].x += p * vv.x; o4[d].y += p * vv.y;
                o4[d].z += p * vv.z; o4[d].w += p * vv.w;
            }
        }
        __syncthreads();
    }

    const float inv = 1.0f / l;
    float4* out = (float4*)(g_attn + ((size_t)b * SS + qg) * DMODEL + h * DK);
    #pragma unroll
    for (int d = 0; d < 16; d++) {
        float4 v = o4[d];
        v.x *= inv; v.y *= inv; v.z *= inv; v.w *= inv;
        out[d] = v;
    }
}

// ---------------------------------------------------------------------------
extern "C" void kernel_launch(void* const* d_in, const int* in_sizes, int n_in,
                              void* d_out, int out_size)
{
    const float* q    = (const float*)d_in[0];
    const float* k    = (const float*)d_in[1];
    const float* v    = (const float*)d_in[2];
    const int*   mask = (const int*)  d_in[3];
    const float* Wq   = (const float*)d_in[4];
    const float* bq   = (const float*)d_in[5];
    const float* Wk   = (const float*)d_in[6];
    const float* bk   = (const float*)d_in[7];
    const float* Wv   = (const float*)d_in[8];
    const float* bv   = (const float*)d_in[9];
    const float* Wo   = (const float*)d_in[10];
    const float* bo   = (const float*)d_in[11];
    float* out = (float*)d_out;

    float *gq, *gk, *gv, *ga;
    cudaGetSymbolAddress((void**)&gq, g_q);
    cudaGetSymbolAddress((void**)&gk, g_k);
    cudaGetSymbolAddress((void**)&gv, g_v);
    cudaGetSymbolAddress((void**)&ga, g_attn);

    dim3 gg(DMODEL / BN, M_ROWS / BM);   // (8, 32)

    gemm_nt<1><<<gg, 256>>>(q, Wq, bq, gq, M_ROWS, DMODEL, DMODEL);
    gemm_nt<1><<<gg, 256>>>(k, Wk, bk, gk, M_ROWS, DMODEL, DMODEL);
    gemm_nt<1><<<gg, 256>>>(v, Wv, bv, gv, M_ROWS, DMODEL, DMODEL);

    attn_kernel<<<dim3(SS / 128, H, BB), 128>>>(mask);

    gemm_nt<0><<<gg, 256>>>(ga, Wo, bo, out, M_ROWS, DMODEL, DMODEL);
}

// round 3
// speedup vs baseline: 1.2285x; 1.2285x over previous
#include <cuda_runtime.h>
#include <cstdint>
#include <cstddef>

#define H 16
#define DMODEL 1024
#define DK 64
#define BB 2
#define SS 2048
#define M_ROWS (BB*SS)   // 4096

typedef unsigned long long u64;

// Scratch (device globals — no allocation allowed)
__device__ float g_q[(size_t)BB*H*SS*DK];
__device__ float g_k[(size_t)BB*H*SS*DK];
__device__ float g_v[(size_t)BB*H*SS*DK];
__device__ float g_attn[(size_t)BB*SS*DMODEL];
__device__ unsigned int g_mbits[(size_t)BB*SS*(SS/32)];

// ---------------------------------------------------------------------------
// f32x2 packed-math helpers (Blackwell full-rate fp32 path)
// ---------------------------------------------------------------------------
__device__ __forceinline__ u64 ffma2(u64 a, u64 b, u64 c) {
    u64 d;
    asm("fma.rn.f32x2 %0, %1, %2, %3;" : "=l"(d) : "l"(a), "l"(b), "l"(c));
    return d;
}
__device__ __forceinline__ u64 fmul2(u64 a, u64 b) {
    u64 d;
    asm("mul.rn.f32x2 %0, %1, %2;" : "=l"(d) : "l"(a), "l"(b));
    return d;
}
__device__ __forceinline__ u64 fadd2(u64 a, u64 b) {
    u64 d;
    asm("add.rn.f32x2 %0, %1, %2;" : "=l"(d) : "l"(a), "l"(b));
    return d;
}
__device__ __forceinline__ u64 pack2(float x, float y) {
    u64 d;
    asm("mov.b64 %0, {%1, %2};" : "=l"(d) : "f"(x), "f"(y));
    return d;
}
__device__ __forceinline__ u64 dup2(float x) {
    u64 d;
    asm("mov.b64 %0, {%1, %1};" : "=l"(d) : "f"(x));
    return d;
}
__device__ __forceinline__ void unpack2(u64 v, float& x, float& y) {
    asm("mov.b64 {%0, %1}, %2;" : "=f"(x), "=f"(y) : "l"(v));
}
__device__ __forceinline__ float ex2(float x) {
    float y;
    asm("ex2.approx.f32 %0, %1;" : "=f"(y) : "f"(x));
    return y;
}

// ---------------------------------------------------------------------------
// Mask bit-pack: g_mbits[b][q][w] bit j = (mask[b][q][w*32+j] != 0)
// ---------------------------------------------------------------------------
__global__ __launch_bounds__(256)
void pack_mask(const int* __restrict__ m)
{
    size_t i = (size_t)blockIdx.x * 256 + threadIdx.x;
    unsigned bit = (m[i] != 0) ? 1u : 0u;
    unsigned w = __ballot_sync(0xffffffff, bit);
    if ((threadIdx.x & 31) == 0) g_mbits[i >> 5] = w;
}

// ---------------------------------------------------------------------------
// SGEMM (f32x2): C = A[M,K] @ W[N,K]^T + bias[N]
// LAYOUT 0: C row-major [M,N].  LAYOUT 1: scatter to head-major [b,h,s,dk].
// ---------------------------------------------------------------------------
#define BM 128
#define BN 128
#define BK 16

template<int LAYOUT>
__global__ __launch_bounds__(256)
void gemm_nt(const float* __restrict__ A, const float* __restrict__ W,
             const float* __restrict__ bias, float* __restrict__ C,
             int M, int N, int K)
{
    __shared__ float As[BK][BM + 4];
    __shared__ float Bs[BK][BN + 4];

    const int tid = threadIdx.x;
    const int tx = tid & 15;
    const int ty = tid >> 4;
    const int m0 = blockIdx.y * BM;
    const int n0 = blockIdx.x * BN;

    u64 acc[8][4];
    #pragma unroll
    for (int i = 0; i < 8; i++)
        #pragma unroll
        for (int j = 0; j < 4; j++) acc[i][j] = 0ULL;

    for (int k0 = 0; k0 < K; k0 += BK) {
        #pragma unroll
        for (int it = 0; it < 2; it++) {
            int idx = tid + it * 256;           // 0..511
            int row = idx >> 2;                 // 0..127
            int kc  = (idx & 3) << 2;           // 0,4,8,12
            float4 av = *(const float4*)&A[(size_t)(m0 + row) * K + k0 + kc];
            As[kc + 0][row] = av.x; As[kc + 1][row] = av.y;
            As[kc + 2][row] = av.z; As[kc + 3][row] = av.w;
            float4 bv = *(const float4*)&W[(size_t)(n0 + row) * K + k0 + kc];
            Bs[kc + 0][row] = bv.x; Bs[kc + 1][row] = bv.y;
            Bs[kc + 2][row] = bv.z; Bs[kc + 3][row] = bv.w;
        }
        __syncthreads();

        #pragma unroll
        for (int kk = 0; kk < BK; kk++) {
            float4 a0 = *(const float4*)&As[kk][ty * 8];
            float4 a1 = *(const float4*)&As[kk][ty * 8 + 4];
            u64 ap[8];
            ap[0] = dup2(a0.x); ap[1] = dup2(a0.y);
            ap[2] = dup2(a0.z); ap[3] = dup2(a0.w);
            ap[4] = dup2(a1.x); ap[5] = dup2(a1.y);
            ap[6] = dup2(a1.z); ap[7] = dup2(a1.w);
            ulonglong2 b01 = *(const ulonglong2*)&Bs[kk][tx * 8];
            ulonglong2 b23 = *(const ulonglong2*)&Bs[kk][tx * 8 + 4];
            u64 bp[4] = { b01.x, b01.y, b23.x, b23.y };
            #pragma unroll
            for (int i = 0; i < 8; i++)
                #pragma unroll
                for (int j = 0; j < 4; j++)
                    acc[i][j] = ffma2(ap[i], bp[j], acc[i][j]);
        }
        __syncthreads();
    }

    #pragma unroll
    for (int i = 0; i < 8; i++) {
        int m = m0 + ty * 8 + i;
        #pragma unroll
        for (int j = 0; j < 4; j++) {
            int n = n0 + tx * 8 + 2 * j;
            u64 bias2 = *(const u64*)&bias[n];
            u64 v2 = fadd2(acc[i][j], bias2);
            if (LAYOUT == 0) {
                *(u64*)&C[(size_t)m * N + n] = v2;
            } else {
                int b  = m >> 11;
                int s  = m & (SS - 1);
                int h  = n >> 6;
                int dk = n & (DK - 1);
                *(u64*)&C[((((size_t)b * H + h) * SS + s) * DK) + dk] = v2;
            }
        }
    }
}

// ---------------------------------------------------------------------------
// GEMM-tiled flash attention (f32x2).
// Block = 64 q-rows for one (b,h). 128 threads as 16(ty) x 8(tx).
// Score microtile: 4q x 8k. PV microtile: 4q x 8d. Key tile KT = 64.
// Smem: Qs[64dk][64q] + (Ks[64dk][64k] union Ps[64k][64q]) + Vs[64k][64d]
//       = exactly 48KB static.
// ---------------------------------------------------------------------------
#define QSCALE 0.18033688011112042f   /* (1/8) * log2(e) */

__global__ __launch_bounds__(128, 3)
void attn_kernel()
{
    __shared__ float Qs[64 * 64];
    __shared__ float KPs[64 * 64];   // Ks (dk-major), later Ps (key-major)
    __shared__ float Vs[64 * 64];

    const int r  = threadIdx.x;
    const int tx = r & 7;
    const int ty = r >> 3;           // 0..15
    const int q0 = blockIdx.x * 64;
    const int h  = blockIdx.y;
    const int bz = blockIdx.z;

    const float* gq = g_q + (((size_t)bz * H + h) * SS) * DK;
    const float* gk = g_k + (((size_t)bz * H + h) * SS) * DK;
    const float* gv = g_v + (((size_t)bz * H + h) * SS) * DK;

    // Load Q tile transposed, pre-scaled by 1/sqrt(dk) * log2e
    #pragma unroll
    for (int it = 0; it < 8; it++) {
        int gid = r + it * 128;      // 0..1023
        int row = gid & 63;
        int c4  = gid >> 6;          // 0..15
        float4 qv = *(const float4*)&gq[(size_t)(q0 + row) * DK + c4 * 4];
        Qs[(c4 * 4 + 0) * 64 + row] = qv.x * QSCALE;
        Qs[(c4 * 4 + 1) * 64 + row] = qv.y * QSCALE;
        Qs[(c4 * 4 + 2) * 64 + row] = qv.z * QSCALE;
        Qs[(c4 * 4 + 3) * 64 + row] = qv.w * QSCALE;
    }

    u64 o2[4][4];
    #pragma unroll
    for (int i = 0; i < 4; i++)
        #pragma unroll
        for (int j = 0; j < 4; j++) o2[i][j] = 0ULL;
    float mrun[4] = { -1e30f, -1e30f, -1e30f, -1e30f };
    float lpart[4] = { 0.f, 0.f, 0.f, 0.f };

    const size_t mbase0 = ((size_t)bz * SS + q0 + ty * 4) * (SS / 32) + (tx >> 2);
    const int sh = (tx & 3) * 8;

    for (int t = 0; t < SS / 64; t++) {
        const int k0 = t * 64;

        // --- load K (transposed into KPs) and V (natural) ---
        #pragma unroll
        for (int it = 0; it < 8; it++) {
            int gid = r + it * 128;
            int row = gid & 63;
            int c4  = gid >> 6;
            float4 kv = *(const float4*)&gk[(size_t)(k0 + row) * DK + c4 * 4];
            KPs[(c4 * 4 + 0) * 64 + row] = kv.x;
            KPs[(c4 * 4 + 1) * 64 + row] = kv.y;
            KPs[(c4 * 4 + 2) * 64 + row] = kv.z;
            KPs[(c4 * 4 + 3) * 64 + row] = kv.w;
        }
        #pragma unroll
        for (int it = 0; it < 8; it++) {
            int idx = r + it * 128;
            int row = idx >> 4;
            int c4  = idx & 15;
            *(float4*)&Vs[row * 64 + c4 * 4] =
                *(const float4*)&gv[(size_t)(k0 + row) * DK + c4 * 4];
        }
        __syncthreads();

        // --- scores: S = Qs^T @ Ks  (4q x 8k per thread) ---
        u64 s2[4][4];
        #pragma unroll
        for (int i = 0; i < 4; i++)
            #pragma unroll
            for (int j = 0; j < 4; j++) s2[i][j] = 0ULL;

        #pragma unroll 8
        for (int kk = 0; kk < 64; kk++) {
            float4 a4 = *(const float4*)&Qs[kk * 64 + ty * 4];
            u64 ap[4] = { dup2(a4.x), dup2(a4.y), dup2(a4.z), dup2(a4.w) };
            ulonglong2 b01 = *(const ulonglong2*)&KPs[kk * 64 + tx * 8];
            ulonglong2 b23 = *(const ulonglong2*)&KPs[kk * 64 + tx * 8 + 4];
            u64 bp[4] = { b01.x, b01.y, b23.x, b23.y };
            #pragma unroll
            for (int i = 0; i < 4; i++)
                #pragma unroll
                for (int j = 0; j < 4; j++)
                    s2[i][j] = ffma2(ap[i], bp[j], s2[i][j]);
        }
        __syncthreads();   // all Ks reads done before Ps overwrite

        // --- masked online softmax ---
        float p[4][8];
        #pragma unroll
        for (int i = 0; i < 4; i++) {
            float sv[8];
            unpack2(s2[i][0], sv[0], sv[1]);
            unpack2(s2[i][1], sv[2], sv[3]);
            unpack2(s2[i][2], sv[4], sv[5]);
            unpack2(s2[i][3], sv[6], sv[7]);
            unsigned mw = g_mbits[mbase0 + (size_t)i * (SS / 32) + (k0 >> 5)];
            float tm = mrun[i];
            #pragma unroll
            for (int j = 0; j < 8; j++) {
                float s = ((mw >> (sh + j)) & 1u) ? sv[j] : -1e30f;
                p[i][j] = s;
                tm = fmaxf(tm, s);
            }
            tm = fmaxf(tm, __shfl_xor_sync(0xffffffff, tm, 1));
            tm = fmaxf(tm, __shfl_xor_sync(0xffffffff, tm, 2));
            tm = fmaxf(tm, __shfl_xor_sync(0xffffffff, tm, 4));
            float alpha = ex2(mrun[i] - tm);
            mrun[i] = tm;
            lpart[i] *= alpha;
            u64 al2 = dup2(alpha);
            #pragma unroll
            for (int j = 0; j < 4; j++) o2[i][j] = fmul2(o2[i][j], al2);
            float ps = 0.f;
            #pragma unroll
            for (int j = 0; j < 8; j++) {
                float pe = ex2(p[i][j] - tm);
                p[i][j] = pe;
                ps += pe;
            }
            lpart[i] += ps;
        }

        // --- store P (key-major, XOR-swizzled columns) ---
        #pragma unroll
        for (int j = 0; j < 8; j++) {
            int key = tx * 8 + j;
            int c4  = ty ^ tx;
            *(float4*)&KPs[key * 64 + c4 * 4] =
                make_float4(p[0][j], p[1][j], p[2][j], p[3][j]);
        }
        __syncthreads();

        // --- O += P @ V  (4q x 8d per thread) ---
        #pragma unroll 8
        for (int kk = 0; kk < 64; kk++) {
            int c4 = ty ^ ((kk >> 3) & 7);
            float4 a4 = *(const float4*)&KPs[kk * 64 + c4 * 4];
            u64 ap[4] = { dup2(a4.x), dup2(a4.y), dup2(a4.z), dup2(a4.w) };
            ulonglong2 v01 = *(const ulonglong2*)&Vs[kk * 64 + tx * 8];
            ulonglong2 v23 = *(const ulonglong2*)&Vs[kk * 64 + tx * 8 + 4];
            u64 vp[4] = { v01.x, v01.y, v23.x, v23.y };
            #pragma unroll
            for (int i = 0; i < 4; i++)
                #pragma unroll
                for (int j = 0; j < 4; j++)
                    o2[i][j] = ffma2(ap[i], vp[j], o2[i][j]);
        }
        __syncthreads();   // before next tile overwrites KPs/Vs
    }

    // --- finalize: divide by row sums, write head-major into g_attn ---
    #pragma unroll
    for (int i = 0; i < 4; i++) {
        float l = lpart[i];
        l += __shfl_xor_sync(0xffffffff, l, 1);
        l += __shfl_xor_sync(0xffffffff, l, 2);
        l += __shfl_xor_sync(0xffffffff, l, 4);
        float inv = 1.0f / l;
        u64 inv2 = dup2(inv);
        size_t base = ((size_t)bz * SS + q0 + ty * 4 + i) * DMODEL + h * DK + tx * 8;
        #pragma unroll
        for (int j = 0; j < 4; j++)
            *(u64*)&g_attn[base + 2 * j] = fmul2(o2[i][j], inv2);
    }
}

// ---------------------------------------------------------------------------
extern "C" void kernel_launch(void* const* d_in, const int* in_sizes, int n_in,
                              void* d_out, int out_size)
{
    const float* q    = (const float*)d_in[0];
    const float* k    = (const float*)d_in[1];
    const float* v    = (const float*)d_in[2];
    const int*   mask = (const int*)  d_in[3];
    const float* Wq   = (const float*)d_in[4];
    const float* bq   = (const float*)d_in[5];
    const float* Wk   = (const float*)d_in[6];
    const float* bk   = (const float*)d_in[7];
    const float* Wv   = (const float*)d_in[8];
    const float* bv   = (const float*)d_in[9];
    const float* Wo   = (const float*)d_in[10];
    const float* bo   = (const float*)d_in[11];
    float* out = (float*)d_out;

    float *gq, *gk, *gv, *ga;
    cudaGetSymbolAddress((void**)&gq, g_q);
    cudaGetSymbolAddress((void**)&gk, g_k);
    cudaGetSymbolAddress((void**)&gv, g_v);
    cudaGetSymbolAddress((void**)&ga, g_attn);

    dim3 gg(DMODEL / BN, M_ROWS / BM);   // (8, 32)

    pack_mask<<<(size_t)BB * SS * SS / 256, 256>>>(mask);
    gemm_nt<1><<<gg, 256>>>(q, Wq, bq, gq, M_ROWS, DMODEL, DMODEL);
    gemm_nt<1><<<gg, 256>>>(k, Wk, bk, gk, M_ROWS, DMODEL, DMODEL);
    gemm_nt<1><<<gg, 256>>>(v, Wv, bv, gv, M_ROWS, DMODEL, DMODEL);

    attn_kernel<<<dim3(SS / 64, H, BB), 128>>>();

    gemm_nt<0><<<gg, 256>>>(ga, Wo, bo, out, M_ROWS, DMODEL, DMODEL);
}

// round 7
// speedup vs baseline: 1.4729x; 1.1990x over previous
#include <cuda_runtime.h>
#include <cuda_bf16.h>
#include <cstdint>
#include <cstddef>

#define H 16
#define DMODEL 1024
#define DK 64
#define BB 2
#define SS 2048
#define M_ROWS (BB*SS)   // 4096

typedef unsigned long long u64;

// Scratch (device globals — no allocation allowed)
__device__ float g_q[(size_t)BB*H*SS*DK];
__device__ float g_k[(size_t)BB*H*SS*DK];
__device__ float g_v[(size_t)BB*H*SS*DK];
__device__ float g_attn[(size_t)BB*SS*DMODEL];
__device__ unsigned int g_mbits[(size_t)BB*SS*(SS/32)];
__device__ __nv_bfloat16 g_inh[(size_t)M_ROWS*DMODEL];
__device__ __nv_bfloat16 g_inl[(size_t)M_ROWS*DMODEL];
__device__ __nv_bfloat16 g_wh[(size_t)DMODEL*DMODEL];
__device__ __nv_bfloat16 g_wl[(size_t)DMODEL*DMODEL];

// ---------------------------------------------------------------------------
// f32x2 packed helpers
// ---------------------------------------------------------------------------
__device__ __forceinline__ u64 ffma2(u64 a, u64 b, u64 c) {
    u64 d; asm("fma.rn.f32x2 %0, %1, %2, %3;" : "=l"(d) : "l"(a), "l"(b), "l"(c)); return d;
}
__device__ __forceinline__ u64 fmul2(u64 a, u64 b) {
    u64 d; asm("mul.rn.f32x2 %0, %1, %2;" : "=l"(d) : "l"(a), "l"(b)); return d;
}
__device__ __forceinline__ u64 pack2(float x, float y) {
    u64 d; asm("mov.b64 %0, {%1, %2};" : "=l"(d) : "f"(x), "f"(y)); return d;
}
__device__ __forceinline__ u64 dup2(float x) {
    u64 d; asm("mov.b64 %0, {%1, %1};" : "=l"(d) : "f"(x)); return d;
}
__device__ __forceinline__ void unpack2(u64 v, float& x, float& y) {
    asm("mov.b64 {%0, %1}, %2;" : "=f"(x), "=f"(y) : "l"(v));
}
__device__ __forceinline__ float ex2(float x) {
    float y; asm("ex2.approx.f32 %0, %1;" : "=f"(y) : "f"(x)); return y;
}
__device__ __forceinline__ uint32_t smem_u32(const void* p) {
    uint32_t a;
    asm("{ .reg .u64 t; cvta.to.shared.u64 t, %1; cvt.u32.u64 %0, t; }" : "=r"(a) : "l"(p));
    return a;
}

// ---------------------------------------------------------------------------
// mma.sync helpers (sm_80 baseline — compiles for sm_100 target)
// ---------------------------------------------------------------------------
#define LDSM4(r, a) \
    asm volatile("ldmatrix.sync.aligned.m8n8.x4.shared.b16 {%0,%1,%2,%3}, [%4];" \
        : "=r"((r)[0]), "=r"((r)[1]), "=r"((r)[2]), "=r"((r)[3]) : "r"(a))
#define LDSM2(r, a) \
    asm volatile("ldmatrix.sync.aligned.m8n8.x2.shared.b16 {%0,%1}, [%2];" \
        : "=r"((r)[0]), "=r"((r)[1]) : "r"(a))
#define MMA16816(d, a, b) \
    asm volatile("mma.sync.aligned.m16n8k16.row.col.f32.bf16.bf16.f32 " \
        "{%0,%1,%2,%3}, {%4,%5,%6,%7}, {%8,%9}, {%0,%1,%2,%3};" \
        : "+f"((d)[0]), "+f"((d)[1]), "+f"((d)[2]), "+f"((d)[3]) \
        : "r"((a)[0]), "r"((a)[1]), "r"((a)[2]), "r"((a)[3]), "r"((b)[0]), "r"((b)[1]))

// ---------------------------------------------------------------------------
// fp32 -> bf16 hi/lo split
// ---------------------------------------------------------------------------
__global__ __launch_bounds__(256)
void conv_split(const float* __restrict__ x, __nv_bfloat16* __restrict__ hi,
                __nv_bfloat16* __restrict__ lo)
{
    size_t i = ((size_t)blockIdx.x * 256 + threadIdx.x) * 4;
    float4 v = *(const float4*)&x[i];
    __nv_bfloat16 h0 = __float2bfloat16(v.x);
    __nv_bfloat16 h1 = __float2bfloat16(v.y);
    __nv_bfloat16 h2 = __float2bfloat16(v.z);
    __nv_bfloat16 h3 = __float2bfloat16(v.w);
    __nv_bfloat16 l0 = __float2bfloat16(v.x - __bfloat162float(h0));
    __nv_bfloat16 l1 = __float2bfloat16(v.y - __bfloat162float(h1));
    __nv_bfloat16 l2 = __float2bfloat16(v.z - __bfloat162float(h2));
    __nv_bfloat16 l3 = __float2bfloat16(v.w - __bfloat162float(h3));
    ushort4 hv, lv;
    hv.x = *(unsigned short*)&h0; hv.y = *(unsigned short*)&h1;
    hv.z = *(unsigned short*)&h2; hv.w = *(unsigned short*)&h3;
    lv.x = *(unsigned short*)&l0; lv.y = *(unsigned short*)&l1;
    lv.z = *(unsigned short*)&l2; lv.w = *(unsigned short*)&l3;
    *(ushort4*)&hi[i] = hv;
    *(ushort4*)&lo[i] = lv;
}

// ---------------------------------------------------------------------------
// Mask bit-pack
// ---------------------------------------------------------------------------
__global__ __launch_bounds__(256)
void pack_mask(const int* __restrict__ m)
{
    size_t i = (size_t)blockIdx.x * 256 + threadIdx.x;
    unsigned bit = (m[i] != 0) ? 1u : 0u;
    unsigned w = __ballot_sync(0xffffffff, bit);
    if ((threadIdx.x & 31) == 0) g_mbits[i >> 5] = w;
}

// ---------------------------------------------------------------------------
// bf16x3 HMMA GEMM: C = A[4096,1024] @ W[1024,1024]^T + bias
// D = Ah*Wh + Ah*Wl + Al*Wh (fp32 accum in registers).
// Block 128x128, K-chunk 32, 256 threads = 8 warps (2m x 4n), warp = 64x32.
// Smem pitch 40 bf16 (80B) -> conflict-free ldmatrix. 41KB static.
// ---------------------------------------------------------------------------
template<int LAYOUT>
__global__ __launch_bounds__(256)
void gemm_mma(const __nv_bfloat16* __restrict__ Ah, const __nv_bfloat16* __restrict__ Al,
              const __nv_bfloat16* __restrict__ Wh, const __nv_bfloat16* __restrict__ Wl,
              const float* __restrict__ bias, float* __restrict__ C)
{
    __shared__ __nv_bfloat16 sAh[128][40];
    __shared__ __nv_bfloat16 sAl[128][40];
    __shared__ __nv_bfloat16 sWh[128][40];
    __shared__ __nv_bfloat16 sWl[128][40];
    __shared__ float bias_sm[128];

    const int tid  = threadIdx.x;
    const int lane = tid & 31;
    const int w    = tid >> 5;
    const int wm   = (w >> 2) * 64;    // 0 or 64
    const int wn   = (w & 3) * 32;     // 0,32,64,96
    const int n0 = blockIdx.x * 128;
    const int m0 = blockIdx.y * 128;

    if (tid < 128) bias_sm[tid] = bias[n0 + tid];

    float acc[4][4][4];
    #pragma unroll
    for (int mt = 0; mt < 4; mt++)
        #pragma unroll
        for (int nt = 0; nt < 4; nt++)
            #pragma unroll
            for (int e = 0; e < 4; e++) acc[mt][nt][e] = 0.f;

    const int lrow = tid >> 1;          // 0..127
    const int lcol = (tid & 1) * 8;     // 0 or 8

    // ldmatrix source addresses (within-warp)
    const int l16 = lane & 15;
    const int a_row = (lane & 15);
    const int a_kof = (lane >> 4) * 8;
    const int b_row = (l16 & 7);
    const int b_kof = (l16 >> 3) * 8;

    for (int c = 0; c < 32; c++) {
        const int k0 = c * 32;
        __syncthreads();   // previous iteration's reads done before overwrite
        #pragma unroll
        for (int half = 0; half < 2; half++) {
            int kk = k0 + half * 16 + lcol;
            int sc = half * 16 + lcol;
            *(uint4*)&sAh[lrow][sc] = *(const uint4*)&Ah[(size_t)(m0 + lrow) * DMODEL + kk];
            *(uint4*)&sAl[lrow][sc] = *(const uint4*)&Al[(size_t)(m0 + lrow) * DMODEL + kk];
            *(uint4*)&sWh[lrow][sc] = *(const uint4*)&Wh[(size_t)(n0 + lrow) * DMODEL + kk];
            *(uint4*)&sWl[lrow][sc] = *(const uint4*)&Wl[(size_t)(n0 + lrow) * DMODEL + kk];
        }
        __syncthreads();

        #pragma unroll
        for (int ks = 0; ks < 2; ks++) {
            uint32_t ah[4][4], al[4][4], bh[4][2], bl[4][2];
            #pragma unroll
            for (int mt = 0; mt < 4; mt++) {
                LDSM4(ah[mt], smem_u32(&sAh[wm + mt * 16 + a_row][ks * 16 + a_kof]));
                LDSM4(al[mt], smem_u32(&sAl[wm + mt * 16 + a_row][ks * 16 + a_kof]));
            }
            #pragma unroll
            for (int nt = 0; nt < 4; nt++) {
                LDSM2(bh[nt], smem_u32(&sWh[wn + nt * 8 + b_row][ks * 16 + b_kof]));
                LDSM2(bl[nt], smem_u32(&sWl[wn + nt * 8 + b_row][ks * 16 + b_kof]));
            }
            #pragma unroll
            for (int mt = 0; mt < 4; mt++)
                #pragma unroll
                for (int nt = 0; nt < 4; nt++) {
                    MMA16816(acc[mt][nt], ah[mt], bh[nt]);
                    MMA16816(acc[mt][nt], ah[mt], bl[nt]);
                    MMA16816(acc[mt][nt], al[mt], bh[nt]);
                }
        }
    }

    // epilogue: thread owns rows (lane>>2) and (lane>>2)+8, cols (lane&3)*2,+1
    const int er = lane >> 2;
    const int ec = (lane & 3) * 2;
    #pragma unroll
    for (int mt = 0; mt < 4; mt++) {
        #pragma unroll
        for (int half = 0; half < 2; half++) {
            int m = m0 + wm + mt * 16 + er + half * 8;
            #pragma unroll
            for (int nt = 0; nt < 4; nt++) {
                int n = n0 + wn + nt * 8 + ec;
                float f0 = acc[mt][nt][half * 2 + 0] + bias_sm[wn + nt * 8 + ec];
                float f1 = acc[mt][nt][half * 2 + 1] + bias_sm[wn + nt * 8 + ec + 1];
                u64 v2 = pack2(f0, f1);
                if (LAYOUT == 0) {
                    *(u64*)&C[(size_t)m * DMODEL + n] = v2;
                } else {
                    int b  = m >> 11;
                    int sq = m & (SS - 1);
                    int hh = n >> 6;
                    int dk = n & (DK - 1);
                    *(u64*)&C[((((size_t)b * H + hh) * SS + sq) * DK) + dk] = v2;
                }
            }
        }
    }
}

// ---------------------------------------------------------------------------
// GEMM-tiled flash attention (f32x2) — unchanged (passing)
// ---------------------------------------------------------------------------
#define QSCALE 0.18033688011112042f   /* (1/8) * log2(e) */

__global__ __launch_bounds__(128, 3)
void attn_kernel()
{
    __shared__ float Qs[64 * 64];
    __shared__ float KPs[64 * 64];
    __shared__ float Vs[64 * 64];

    const int r  = threadIdx.x;
    const int tx = r & 7;
    const int ty = r >> 3;
    const int q0 = blockIdx.x * 64;
    const int h  = blockIdx.y;
    const int bz = blockIdx.z;

    const float* gq = g_q + (((size_t)bz * H + h) * SS) * DK;
    const float* gk = g_k + (((size_t)bz * H + h) * SS) * DK;
    const float* gv = g_v + (((size_t)bz * H + h) * SS) * DK;

    #pragma unroll
    for (int it = 0; it < 8; it++) {
        int gid = r + it * 128;
        int row = gid & 63;
        int c4  = gid >> 6;
        float4 qv = *(const float4*)&gq[(size_t)(q0 + row) * DK + c4 * 4];
        Qs[(c4 * 4 + 0) * 64 + row] = qv.x * QSCALE;
        Qs[(c4 * 4 + 1) * 64 + row] = qv.y * QSCALE;
        Qs[(c4 * 4 + 2) * 64 + row] = qv.z * QSCALE;
        Qs[(c4 * 4 + 3) * 64 + row] = qv.w * QSCALE;
    }

    u64 o2[4][4];
    #pragma unroll
    for (int i = 0; i < 4; i++)
        #pragma unroll
        for (int j = 0; j < 4; j++) o2[i][j] = 0ULL;
    float mrun[4] = { -1e30f, -1e30f, -1e30f, -1e30f };
    float lpart[4] = { 0.f, 0.f, 0.f, 0.f };

    const size_t mbase0 = ((size_t)bz * SS + q0 + ty * 4) * (SS / 32) + (tx >> 2);
    const int sh = (tx & 3) * 8;

    for (int t = 0; t < SS / 64; t++) {
        const int k0 = t * 64;

        #pragma unroll
        for (int it = 0; it < 8; it++) {
            int gid = r + it * 128;
            int row = gid & 63;
            int c4  = gid >> 6;
            float4 kv = *(const float4*)&gk[(size_t)(k0 + row) * DK + c4 * 4];
            KPs[(c4 * 4 + 0) * 64 + row] = kv.x;
            KPs[(c4 * 4 + 1) * 64 + row] = kv.y;
            KPs[(c4 * 4 + 2) * 64 + row] = kv.z;
            KPs[(c4 * 4 + 3) * 64 + row] = kv.w;
        }
        #pragma unroll
        for (int it = 0; it < 8; it++) {
            int idx = r + it * 128;
            int row = idx >> 4;
            int c4  = idx & 15;
            *(float4*)&Vs[row * 64 + c4 * 4] =
                *(const float4*)&gv[(size_t)(k0 + row) * DK + c4 * 4];
        }
        __syncthreads();

        u64 s2[4][4];
        #pragma unroll
        for (int i = 0; i < 4; i++)
            #pragma unroll
            for (int j = 0; j < 4; j++) s2[i][j] = 0ULL;

        #pragma unroll 8
        for (int kk = 0; kk < 64; kk++) {
            float4 a4 = *(const float4*)&Qs[kk * 64 + ty * 4];
            u64 ap[4] = { dup2(a4.x), dup2(a4.y), dup2(a4.z), dup2(a4.w) };
            ulonglong2 b01 = *(const ulonglong2*)&KPs[kk * 64 + tx * 8];
            ulonglong2 b23 = *(const ulonglong2*)&KPs[kk * 64 + tx * 8 + 4];
            u64 bp[4] = { b01.x, b01.y, b23.x, b23.y };
            #pragma unroll
            for (int i = 0; i < 4; i++)
                #pragma unroll
                for (int j = 0; j < 4; j++)
                    s2[i][j] = ffma2(ap[i], bp[j], s2[i][j]);
        }
        __syncthreads();

        float p[4][8];
        #pragma unroll
        for (int i = 0; i < 4; i++) {
            float sv[8];
            unpack2(s2[i][0], sv[0], sv[1]);
            unpack2(s2[i][1], sv[2], sv[3]);
            unpack2(s2[i][2], sv[4], sv[5]);
            unpack2(s2[i][3], sv[6], sv[7]);
            unsigned mw = g_mbits[mbase0 + (size_t)i * (SS / 32) + (k0 >> 5)];
            float tm = mrun[i];
            #pragma unroll
            for (int j = 0; j < 8; j++) {
                float s = ((mw >> (sh + j)) & 1u) ? sv[j] : -1e30f;
                p[i][j] = s;
                tm = fmaxf(tm, s);
            }
            tm = fmaxf(tm, __shfl_xor_sync(0xffffffff, tm, 1));
            tm = fmaxf(tm, __shfl_xor_sync(0xffffffff, tm, 2));
            tm = fmaxf(tm, __shfl_xor_sync(0xffffffff, tm, 4));
            float alpha = ex2(mrun[i] - tm);
            mrun[i] = tm;
            lpart[i] *= alpha;
            u64 al2 = dup2(alpha);
            #pragma unroll
            for (int j = 0; j < 4; j++) o2[i][j] = fmul2(o2[i][j], al2);
            float ps = 0.f;
            #pragma unroll
            for (int j = 0; j < 8; j++) {
                float pe = ex2(p[i][j] - tm);
                p[i][j] = pe;
                ps += pe;
            }
            lpart[i] += ps;
        }

        #pragma unroll
        for (int j = 0; j < 8; j++) {
            int key = tx * 8 + j;
            int c4  = ty ^ tx;
            *(float4*)&KPs[key * 64 + c4 * 4] =
                make_float4(p[0][j], p[1][j], p[2][j], p[3][j]);
        }
        __syncthreads();

        #pragma unroll 8
        for (int kk = 0; kk < 64; kk++) {
            int c4 = ty ^ ((kk >> 3) & 7);
            float4 a4 = *(const float4*)&KPs[kk * 64 + c4 * 4];
            u64 ap[4] = { dup2(a4.x), dup2(a4.y), dup2(a4.z), dup2(a4.w) };
            ulonglong2 v01 = *(const ulonglong2*)&Vs[kk * 64 + tx * 8];
            ulonglong2 v23 = *(const ulonglong2*)&Vs[kk * 64 + tx * 8 + 4];
            u64 vp[4] = { v01.x, v01.y, v23.x, v23.y };
            #pragma unroll
            for (int i = 0; i < 4; i++)
                #pragma unroll
                for (int j = 0; j < 4; j++)
                    o2[i][j] = ffma2(ap[i], vp[j], o2[i][j]);
        }
        __syncthreads();
    }

    #pragma unroll
    for (int i = 0; i < 4; i++) {
        float l = lpart[i];
        l += __shfl_xor_sync(0xffffffff, l, 1);
        l += __shfl_xor_sync(0xffffffff, l, 2);
        l += __shfl_xor_sync(0xffffffff, l, 4);
        float inv = 1.0f / l;
        u64 inv2 = dup2(inv);
        size_t base = ((size_t)bz * SS + q0 + ty * 4 + i) * DMODEL + h * DK + tx * 8;
        #pragma unroll
        for (int j = 0; j < 4; j++)
            *(u64*)&g_attn[base + 2 * j] = fmul2(o2[i][j], inv2);
    }
}

// ---------------------------------------------------------------------------
extern "C" void kernel_launch(void* const* d_in, const int* in_sizes, int n_in,
                              void* d_out, int out_size)
{
    const float* q    = (const float*)d_in[0];
    const float* k    = (const float*)d_in[1];
    const float* v    = (const float*)d_in[2];
    const int*   mask = (const int*)  d_in[3];
    const float* Wq   = (const float*)d_in[4];
    const float* bq   = (const float*)d_in[5];
    const float* Wk   = (const float*)d_in[6];
    const float* bk   = (const float*)d_in[7];
    const float* Wv   = (const float*)d_in[8];
    const float* bv   = (const float*)d_in[9];
    const float* Wo   = (const float*)d_in[10];
    const float* bo   = (const float*)d_in[11];
    float* out = (float*)d_out;

    float *gq, *gk, *gv, *ga;
    __nv_bfloat16 *ih, *il, *wh, *wl;
    cudaGetSymbolAddress((void**)&gq, g_q);
    cudaGetSymbolAddress((void**)&gk, g_k);
    cudaGetSymbolAddress((void**)&gv, g_v);
    cudaGetSymbolAddress((void**)&ga, g_attn);
    cudaGetSymbolAddress((void**)&ih, g_inh);
    cudaGetSymbolAddress((void**)&il, g_inl);
    cudaGetSymbolAddress((void**)&wh, g_wh);
    cudaGetSymbolAddress((void**)&wl, g_wl);

    const int ACT_BLKS = (M_ROWS * DMODEL) / (256 * 4);   // 4096
    const int W_BLKS   = (DMODEL * DMODEL) / (256 * 4);   // 1024
    dim3 gg(DMODEL / 128, M_ROWS / 128);                   // (8, 32)

    pack_mask<<<(size_t)BB * SS * SS / 256, 256>>>(mask);

    conv_split<<<ACT_BLKS, 256>>>(q, ih, il);
    conv_split<<<W_BLKS, 256>>>(Wq, wh, wl);
    gemm_mma<1><<<gg, 256>>>(ih, il, wh, wl, bq, gq);

    conv_split<<<ACT_BLKS, 256>>>(k, ih, il);
    conv_split<<<W_BLKS, 256>>>(Wk, wh, wl);
    gemm_mma<1><<<gg, 256>>>(ih, il, wh, wl, bk, gk);

    conv_split<<<ACT_BLKS, 256>>>(v, ih, il);
    conv_split<<<W_BLKS, 256>>>(Wv, wh, wl);
    gemm_mma<1><<<gg, 256>>>(ih, il, wh, wl, bv, gv);

    attn_kernel<<<dim3(SS / 64, H, BB), 128>>>();

    conv_split<<<ACT_BLKS, 256>>>(ga, ih, il);
    conv_split<<<W_BLKS, 256>>>(Wo, wh, wl);
    gemm_mma<0><<<gg, 256>>>(ih, il, wh, wl, bo, out);
}

// round 8
// speedup vs baseline: 2.8306x; 1.9218x over previous
#include <cuda_runtime.h>
#include <cuda_bf16.h>
#include <cstdint>
#include <cstddef>

#define H 16
#define DMODEL 1024
#define DK 64
#define BB 2
#define SS 2048
#define M_ROWS (BB*SS)   // 4096

typedef unsigned long long u64;

// Scratch (device globals — no allocation allowed)
__device__ unsigned int g_mbits[(size_t)BB*SS*(SS/32)];
// head-major [b,h,s,dk] bf16 hi/lo Q/K/V (written by projection epilogue)
__device__ __nv_bfloat16 g_qh[(size_t)BB*H*SS*DK];
__device__ __nv_bfloat16 g_ql[(size_t)BB*H*SS*DK];
__device__ __nv_bfloat16 g_kh[(size_t)BB*H*SS*DK];
__device__ __nv_bfloat16 g_kl[(size_t)BB*H*SS*DK];
__device__ __nv_bfloat16 g_vh[(size_t)BB*H*SS*DK];
__device__ __nv_bfloat16 g_vl[(size_t)BB*H*SS*DK];
// activation / weight hi-lo split buffers
__device__ __nv_bfloat16 g_inh[(size_t)M_ROWS*DMODEL];
__device__ __nv_bfloat16 g_inl[(size_t)M_ROWS*DMODEL];
__device__ __nv_bfloat16 g_wh[(size_t)DMODEL*DMODEL];
__device__ __nv_bfloat16 g_wl[(size_t)DMODEL*DMODEL];

#define QSCALE 0.18033688011112042f   /* (1/8) * log2(e) */
#define MASKVAL (-14427.0f)           /* -10000 * log2(e)  */

// ---------------------------------------------------------------------------
// helpers
// ---------------------------------------------------------------------------
__device__ __forceinline__ u64 pack2(float x, float y) {
    u64 d; asm("mov.b64 %0, {%1, %2};" : "=l"(d) : "f"(x), "f"(y)); return d;
}
__device__ __forceinline__ float ex2(float x) {
    float y; asm("ex2.approx.f32 %0, %1;" : "=f"(y) : "f"(x)); return y;
}
__device__ __forceinline__ uint32_t smem_u32(const void* p) {
    uint32_t a;
    asm("{ .reg .u64 t; cvta.to.shared.u64 t, %1; cvt.u32.u64 %0, t; }" : "=r"(a) : "l"(p));
    return a;
}
// split (x,y) into bf16x2 hi + bf16x2 lo-residual
__device__ __forceinline__ void split_pair(float x, float y, uint32_t& hi, uint32_t& lo) {
    __nv_bfloat162 hp = __floats2bfloat162_rn(x, y);
    float rx = x - __bfloat162float(hp.x);
    float ry = y - __bfloat162float(hp.y);
    __nv_bfloat162 lp2 = __floats2bfloat162_rn(rx, ry);
    hi = *(uint32_t*)&hp; lo = *(uint32_t*)&lp2;
}

#define LDSM4(r, a) \
    asm volatile("ldmatrix.sync.aligned.m8n8.x4.shared.b16 {%0,%1,%2,%3}, [%4];" \
        : "=r"((r)[0]), "=r"((r)[1]), "=r"((r)[2]), "=r"((r)[3]) : "r"(a))
#define LDSM2(r, a) \
    asm volatile("ldmatrix.sync.aligned.m8n8.x2.shared.b16 {%0,%1}, [%2];" \
        : "=r"((r)[0]), "=r"((r)[1]) : "r"(a))
#define LDSM2T(r, a) \
    asm volatile("ldmatrix.sync.aligned.m8n8.x2.trans.shared.b16 {%0,%1}, [%2];" \
        : "=r"((r)[0]), "=r"((r)[1]) : "r"(a))
#define MMA16816(d, a, b) \
    asm volatile("mma.sync.aligned.m16n8k16.row.col.f32.bf16.bf16.f32 " \
        "{%0,%1,%2,%3}, {%4,%5,%6,%7}, {%8,%9}, {%0,%1,%2,%3};" \
        : "+f"((d)[0]), "+f"((d)[1]), "+f"((d)[2]), "+f"((d)[3]) \
        : "r"((a)[0]), "r"((a)[1]), "r"((a)[2]), "r"((a)[3]), "r"((b)[0]), "r"((b)[1]))

// ---------------------------------------------------------------------------
// fp32 -> bf16 hi/lo split
// ---------------------------------------------------------------------------
__global__ __launch_bounds__(256)
void conv_split(const float* __restrict__ x, __nv_bfloat16* __restrict__ hi,
                __nv_bfloat16* __restrict__ lo)
{
    size_t i = ((size_t)blockIdx.x * 256 + threadIdx.x) * 4;
    float4 v = *(const float4*)&x[i];
    uint32_t h0, l0, h1, l1;
    split_pair(v.x, v.y, h0, l0);
    split_pair(v.z, v.w, h1, l1);
    *(uint2*)&hi[i] = make_uint2(h0, h1);
    *(uint2*)&lo[i] = make_uint2(l0, l1);
}

// ---------------------------------------------------------------------------
// Mask bit-pack
// ---------------------------------------------------------------------------
__global__ __launch_bounds__(256)
void pack_mask(const int* __restrict__ m)
{
    size_t i = (size_t)blockIdx.x * 256 + threadIdx.x;
    unsigned bit = (m[i] != 0) ? 1u : 0u;
    unsigned w = __ballot_sync(0xffffffff, bit);
    if ((threadIdx.x & 31) == 0) g_mbits[i >> 5] = w;
}

// ---------------------------------------------------------------------------
// bf16x3 HMMA GEMM: out = A[4096,1024] @ W[1024,1024]^T + bias
// LAYOUT 0: fp32 row-major to C.
// LAYOUT 1: bf16 hi/lo head-major to Chi/Clo, scaled by `scale`.
// ---------------------------------------------------------------------------
template<int LAYOUT>
__global__ __launch_bounds__(256)
void gemm_mma(const __nv_bfloat16* __restrict__ Ah, const __nv_bfloat16* __restrict__ Al,
              const __nv_bfloat16* __restrict__ Wh, const __nv_bfloat16* __restrict__ Wl,
              const float* __restrict__ bias, float* __restrict__ C,
              __nv_bfloat16* __restrict__ Chi, __nv_bfloat16* __restrict__ Clo,
              float scale)
{
    __shared__ __nv_bfloat16 sAh[128][40];
    __shared__ __nv_bfloat16 sAl[128][40];
    __shared__ __nv_bfloat16 sWh[128][40];
    __shared__ __nv_bfloat16 sWl[128][40];
    __shared__ float bias_sm[128];

    const int tid  = threadIdx.x;
    const int lane = tid & 31;
    const int w    = tid >> 5;
    const int wm   = (w >> 2) * 64;
    const int wn   = (w & 3) * 32;
    const int n0 = blockIdx.x * 128;
    const int m0 = blockIdx.y * 128;

    if (tid < 128) bias_sm[tid] = bias[n0 + tid];

    float acc[4][4][4];
    #pragma unroll
    for (int mt = 0; mt < 4; mt++)
        #pragma unroll
        for (int nt = 0; nt < 4; nt++)
            #pragma unroll
            for (int e = 0; e < 4; e++) acc[mt][nt][e] = 0.f;

    const int lrow = tid >> 1;
    const int lcol = (tid & 1) * 8;
    const int l16 = lane & 15;
    const int a_row = (lane & 15);
    const int a_kof = (lane >> 4) * 8;
    const int b_row = (l16 & 7);
    const int b_kof = (l16 >> 3) * 8;

    for (int c = 0; c < 32; c++) {
        const int k0 = c * 32;
        __syncthreads();
        #pragma unroll
        for (int half = 0; half < 2; half++) {
            int kk = k0 + half * 16 + lcol;
            int sc = half * 16 + lcol;
            *(uint4*)&sAh[lrow][sc] = *(const uint4*)&Ah[(size_t)(m0 + lrow) * DMODEL + kk];
            *(uint4*)&sAl[lrow][sc] = *(const uint4*)&Al[(size_t)(m0 + lrow) * DMODEL + kk];
            *(uint4*)&sWh[lrow][sc] = *(const uint4*)&Wh[(size_t)(n0 + lrow) * DMODEL + kk];
            *(uint4*)&sWl[lrow][sc] = *(const uint4*)&Wl[(size_t)(n0 + lrow) * DMODEL + kk];
        }
        __syncthreads();

        #pragma unroll
        for (int ks = 0; ks < 2; ks++) {
            uint32_t ah[4][4], al[4][4], bh[4][2], bl[4][2];
            #pragma unroll
            for (int mt = 0; mt < 4; mt++) {
                LDSM4(ah[mt], smem_u32(&sAh[wm + mt * 16 + a_row][ks * 16 + a_kof]));
                LDSM4(al[mt], smem_u32(&sAl[wm + mt * 16 + a_row][ks * 16 + a_kof]));
            }
            #pragma unroll
            for (int nt = 0; nt < 4; nt++) {
                LDSM2(bh[nt], smem_u32(&sWh[wn + nt * 8 + b_row][ks * 16 + b_kof]));
                LDSM2(bl[nt], smem_u32(&sWl[wn + nt * 8 + b_row][ks * 16 + b_kof]));
            }
            #pragma unroll
            for (int mt = 0; mt < 4; mt++)
                #pragma unroll
                for (int nt = 0; nt < 4; nt++) {
                    MMA16816(acc[mt][nt], ah[mt], bh[nt]);
                    MMA16816(acc[mt][nt], ah[mt], bl[nt]);
                    MMA16816(acc[mt][nt], al[mt], bh[nt]);
                }
        }
    }

    const int er = lane >> 2;
    const int ec = (lane & 3) * 2;
    #pragma unroll
    for (int mt = 0; mt < 4; mt++) {
        #pragma unroll
        for (int half = 0; half < 2; half++) {
            int m = m0 + wm + mt * 16 + er + half * 8;
            #pragma unroll
            for (int nt = 0; nt < 4; nt++) {
                int n = n0 + wn + nt * 8 + ec;
                float f0 = (acc[mt][nt][half * 2 + 0] + bias_sm[wn + nt * 8 + ec]) * scale;
                float f1 = (acc[mt][nt][half * 2 + 1] + bias_sm[wn + nt * 8 + ec + 1]) * scale;
                if (LAYOUT == 0) {
                    *(u64*)&C[(size_t)m * DMODEL + n] = pack2(f0, f1);
                } else {
                    int b  = m >> 11;
                    int sq = m & (SS - 1);
                    int hh = n >> 6;
                    int dk = n & (DK - 1);
                    size_t o = ((((size_t)b * H + hh) * SS + sq) * DK) + dk;
                    uint32_t hi, lo;
                    split_pair(f0, f1, hi, lo);
                    *(uint32_t*)&Chi[o] = hi;
                    *(uint32_t*)&Clo[o] = lo;
                }
            }
        }
    }
}

// ---------------------------------------------------------------------------
// HMMA flash attention (bf16x3). Block = 64 q-rows x one (b,h), 128 threads.
// Warp layout 8m x 1n: warp = 16q x 32keys -> softmax reductions in-warp.
// P stays in registers (score accs map directly onto A fragments).
// ---------------------------------------------------------------------------
__global__ __launch_bounds__(128)
void attn_mma()
{
    __shared__ __nv_bfloat16 sQh[64][72], sQl[64][72];
    __shared__ __nv_bfloat16 sKh[32][72], sKl[32][72];
    __shared__ __nv_bfloat16 sVh[32][72], sVl[32][72];

    const int tid  = threadIdx.x;
    const int lane = tid & 31;
    const int w    = tid >> 5;       // 0..3
    const int wq   = w * 16;
    const int q0 = blockIdx.x * 64;
    const int h  = blockIdx.y;
    const int bz = blockIdx.z;

    const size_t hb = ((size_t)bz * H + h) * SS;
    const __nv_bfloat16* gqh = g_qh + (hb + q0) * DK;
    const __nv_bfloat16* gql = g_ql + (hb + q0) * DK;
    const __nv_bfloat16* gkh = g_kh + hb * DK;
    const __nv_bfloat16* gkl = g_kl + hb * DK;
    const __nv_bfloat16* gvh = g_vh + hb * DK;
    const __nv_bfloat16* gvl = g_vl + hb * DK;

    // load Q tile (64 x 64), 512 uint4 chunks over 128 threads
    #pragma unroll
    for (int i = 0; i < 4; i++) {
        int idx = tid + i * 128;
        int row = idx >> 3, c8 = idx & 7;
        *(uint4*)&sQh[row][c8 * 8] = *(const uint4*)(gqh + (size_t)row * DK + c8 * 8);
        *(uint4*)&sQl[row][c8 * 8] = *(const uint4*)(gql + (size_t)row * DK + c8 * 8);
    }

    float acc[8][4];
    #pragma unroll
    for (int nt = 0; nt < 8; nt++)
        #pragma unroll
        for (int e = 0; e < 4; e++) acc[nt][e] = 0.f;
    float mrun0 = -1e30f, mrun1 = -1e30f;
    float lp0 = 0.f, lp1 = 0.f;

    const int er = lane >> 2, ec = (lane & 3) * 2;
    const int a_row = lane & 15, a_kof = (lane >> 4) * 8;
    const int l16 = lane & 15;
    const int b_row = l16 & 7, b_kof = (l16 >> 3) * 8;

    const size_t mrow0 = ((size_t)bz * SS + q0 + wq + er) * (SS / 32);
    const size_t mrow1 = mrow0 + 8 * (SS / 32);

    for (int t = 0; t < SS / 32; t++) {
        const int k0 = t * 32;
        __syncthreads();
        #pragma unroll
        for (int i = 0; i < 2; i++) {
            int idx = tid + i * 128;
            int row = idx >> 3, c8 = idx & 7;
            size_t go = (size_t)(k0 + row) * DK + c8 * 8;
            *(uint4*)&sKh[row][c8 * 8] = *(const uint4*)(gkh + go);
            *(uint4*)&sKl[row][c8 * 8] = *(const uint4*)(gkl + go);
            *(uint4*)&sVh[row][c8 * 8] = *(const uint4*)(gvh + go);
            *(uint4*)&sVl[row][c8 * 8] = *(const uint4*)(gvl + go);
        }
        __syncthreads();

        // --- scores: 16q x 32k per warp ---
        float sc[4][4];
        #pragma unroll
        for (int nt = 0; nt < 4; nt++)
            #pragma unroll
            for (int e = 0; e < 4; e++) sc[nt][e] = 0.f;

        #pragma unroll
        for (int ks = 0; ks < 4; ks++) {
            uint32_t ah[4], al[4];
            LDSM4(ah, smem_u32(&sQh[wq + a_row][ks * 16 + a_kof]));
            LDSM4(al, smem_u32(&sQl[wq + a_row][ks * 16 + a_kof]));
            #pragma unroll
            for (int nt = 0; nt < 4; nt++) {
                uint32_t bh[2], bl[2];
                LDSM2(bh, smem_u32(&sKh[nt * 8 + b_row][ks * 16 + b_kof]));
                LDSM2(bl, smem_u32(&sKl[nt * 8 + b_row][ks * 16 + b_kof]));
                MMA16816(sc[nt], ah, bh);
                MMA16816(sc[nt], ah, bl);
                MMA16816(sc[nt], al, bh);
            }
        }

        // --- mask + online softmax ---
        unsigned mw0 = g_mbits[mrow0 + t];
        unsigned mw1 = g_mbits[mrow1 + t];
        #pragma unroll
        for (int nt = 0; nt < 4; nt++) {
            int j0 = nt * 8 + ec;
            if (!((mw0 >> j0) & 1u))       sc[nt][0] = MASKVAL;
            if (!((mw0 >> (j0 + 1)) & 1u)) sc[nt][1] = MASKVAL;
            if (!((mw1 >> j0) & 1u))       sc[nt][2] = MASKVAL;
            if (!((mw1 >> (j0 + 1)) & 1u)) sc[nt][3] = MASKVAL;
        }
        float m0 = mrun0, m1 = mrun1;
        #pragma unroll
        for (int nt = 0; nt < 4; nt++) {
            m0 = fmaxf(m0, fmaxf(sc[nt][0], sc[nt][1]));
            m1 = fmaxf(m1, fmaxf(sc[nt][2], sc[nt][3]));
        }
        m0 = fmaxf(m0, __shfl_xor_sync(0xffffffff, m0, 1));
        m0 = fmaxf(m0, __shfl_xor_sync(0xffffffff, m0, 2));
        m1 = fmaxf(m1, __shfl_xor_sync(0xffffffff, m1, 1));
        m1 = fmaxf(m1, __shfl_xor_sync(0xffffffff, m1, 2));
        float al0 = ex2(mrun0 - m0);
        float al1 = ex2(mrun1 - m1);
        mrun0 = m0; mrun1 = m1;
        lp0 *= al0; lp1 *= al1;
        #pragma unroll
        for (int nt = 0; nt < 8; nt++) {
            acc[nt][0] *= al0; acc[nt][1] *= al0;
            acc[nt][2] *= al1; acc[nt][3] *= al1;
        }
        float s0 = 0.f, s1 = 0.f;
        #pragma unroll
        for (int nt = 0; nt < 4; nt++) {
            sc[nt][0] = ex2(sc[nt][0] - m0); s0 += sc[nt][0];
            sc[nt][1] = ex2(sc[nt][1] - m0); s0 += sc[nt][1];
            sc[nt][2] = ex2(sc[nt][2] - m1); s1 += sc[nt][2];
            sc[nt][3] = ex2(sc[nt][3] - m1); s1 += sc[nt][3];
        }
        lp0 += s0; lp1 += s1;

        // --- PV: P fragments straight from score registers ---
        #pragma unroll
        for (int t2 = 0; t2 < 2; t2++) {
            uint32_t ph[4], pl[4];
            split_pair(sc[2*t2][0],   sc[2*t2][1],   ph[0], pl[0]);
            split_pair(sc[2*t2][2],   sc[2*t2][3],   ph[1], pl[1]);
            split_pair(sc[2*t2+1][0], sc[2*t2+1][1], ph[2], pl[2]);
            split_pair(sc[2*t2+1][2], sc[2*t2+1][3], ph[3], pl[3]);
            #pragma unroll
            for (int nt = 0; nt < 8; nt++) {
                uint32_t vh[2], vl[2];
                LDSM2T(vh, smem_u32(&sVh[t2 * 16 + l16][nt * 8]));
                LDSM2T(vl, smem_u32(&sVl[t2 * 16 + l16][nt * 8]));
                MMA16816(acc[nt], ph, vh);
                MMA16816(acc[nt], ph, vl);
                MMA16816(acc[nt], pl, vh);
            }
        }
    }

    // --- finalize ---
    lp0 += __shfl_xor_sync(0xffffffff, lp0, 1);
    lp0 += __shfl_xor_sync(0xffffffff, lp0, 2);
    lp1 += __shfl_xor_sync(0xffffffff, lp1, 1);
    lp1 += __shfl_xor_sync(0xffffffff, lp1, 2);
    float inv0 = 1.0f / lp0;
    float inv1 = 1.0f / lp1;

    size_t ro0 = ((size_t)bz * SS + q0 + wq + er) * DMODEL + (size_t)h * DK;
    size_t ro1 = ro0 + 8 * DMODEL;
    #pragma unroll
    for (int nt = 0; nt < 8; nt++) {
        int c = nt * 8 + ec;
        uint32_t hi, lo;
        split_pair(acc[nt][0] * inv0, acc[nt][1] * inv0, hi, lo);
        *(uint32_t*)&g_inh[ro0 + c] = hi;
        *(uint32_t*)&g_inl[ro0 + c] = lo;
        split_pair(acc[nt][2] * inv1, acc[nt][3] * inv1, hi, lo);
        *(uint32_t*)&g_inh[ro1 + c] = hi;
        *(uint32_t*)&g_inl[ro1 + c] = lo;
    }
}

// ---------------------------------------------------------------------------
extern "C" void kernel_launch(void* const* d_in, const int* in_sizes, int n_in,
                              void* d_out, int out_size)
{
    const float* q    = (const float*)d_in[0];
    const float* k    = (const float*)d_in[1];
    const float* v    = (const float*)d_in[2];
    const int*   mask = (const int*)  d_in[3];
    const float* Wq   = (const float*)d_in[4];
    const float* bq   = (const float*)d_in[5];
    const float* Wk   = (const float*)d_in[6];
    const float* bk   = (const float*)d_in[7];
    const float* Wv   = (const float*)d_in[8];
    const float* bv   = (const float*)d_in[9];
    const float* Wo   = (const float*)d_in[10];
    const float* bo   = (const float*)d_in[11];
    float* out = (float*)d_out;

    __nv_bfloat16 *ih, *il, *wh, *wl, *qh, *ql, *kh, *kl, *vh, *vl;
    cudaGetSymbolAddress((void**)&ih, g_inh);
    cudaGetSymbolAddress((void**)&il, g_inl);
    cudaGetSymbolAddress((void**)&wh, g_wh);
    cudaGetSymbolAddress((void**)&wl, g_wl);
    cudaGetSymbolAddress((void**)&qh, g_qh);
    cudaGetSymbolAddress((void**)&ql, g_ql);
    cudaGetSymbolAddress((void**)&kh, g_kh);
    cudaGetSymbolAddress((void**)&kl, g_kl);
    cudaGetSymbolAddress((void**)&vh, g_vh);
    cudaGetSymbolAddress((void**)&vl, g_vl);

    const int ACT_BLKS = (M_ROWS * DMODEL) / (256 * 4);   // 4096
    const int W_BLKS   = (DMODEL * DMODEL) / (256 * 4);   // 1024
    dim3 gg(DMODEL / 128, M_ROWS / 128);                   // (8, 32)

    pack_mask<<<(size_t)BB * SS * SS / 256, 256>>>(mask);

    conv_split<<<ACT_BLKS, 256>>>(q, ih, il);
    conv_split<<<W_BLKS, 256>>>(Wq, wh, wl);
    gemm_mma<1><<<gg, 256>>>(ih, il, wh, wl, bq, nullptr, qh, ql, QSCALE);

    conv_split<<<ACT_BLKS, 256>>>(k, ih, il);
    conv_split<<<W_BLKS, 256>>>(Wk, wh, wl);
    gemm_mma<1><<<gg, 256>>>(ih, il, wh, wl, bk, nullptr, kh, kl, 1.0f);

    conv_split<<<ACT_BLKS, 256>>>(v, ih, il);
    conv_split<<<W_BLKS, 256>>>(Wv, wh, wl);
    gemm_mma<1><<<gg, 256>>>(ih, il, wh, wl, bv, nullptr, vh, vl, 1.0f);

    attn_mma<<<dim3(SS / 64, H, BB), 128>>>();

    conv_split<<<W_BLKS, 256>>>(Wo, wh, wl);
    gemm_mma<0><<<gg, 256>>>(ih, il, wh, wl, bo, out, nullptr, nullptr, 1.0f);
}

// round 9
// speedup vs baseline: 3.1895x; 1.1268x over previous
#include <cuda_runtime.h>
#include <cuda_bf16.h>
#include <cstdint>
#include <cstddef>

#define H 16
#define DMODEL 1024
#define DK 64
#define BB 2
#define SS 2048
#define M_ROWS (BB*SS)   // 4096

typedef unsigned long long u64;

// Scratch (device globals — no allocation allowed)
__device__ unsigned int g_mbits[(size_t)BB*SS*(SS/32)];
__device__ __nv_bfloat16 g_qh[(size_t)BB*H*SS*DK];
__device__ __nv_bfloat16 g_ql[(size_t)BB*H*SS*DK];
__device__ __nv_bfloat16 g_kh[(size_t)BB*H*SS*DK];
__device__ __nv_bfloat16 g_kl[(size_t)BB*H*SS*DK];
__device__ __nv_bfloat16 g_vh[(size_t)BB*H*SS*DK];
__device__ __nv_bfloat16 g_vl[(size_t)BB*H*SS*DK];
__device__ __nv_bfloat16 g_inh[(size_t)M_ROWS*DMODEL];
__device__ __nv_bfloat16 g_inl[(size_t)M_ROWS*DMODEL];
__device__ __nv_bfloat16 g_wh[(size_t)DMODEL*DMODEL];
__device__ __nv_bfloat16 g_wl[(size_t)DMODEL*DMODEL];

#define QSCALE 0.18033688011112042f   /* (1/8) * log2(e) */
#define MASKVAL (-14427.0f)           /* -10000 * log2(e)  */

// ---------------------------------------------------------------------------
// helpers
// ---------------------------------------------------------------------------
__device__ __forceinline__ u64 pack2(float x, float y) {
    u64 d; asm("mov.b64 %0, {%1, %2};" : "=l"(d) : "f"(x), "f"(y)); return d;
}
__device__ __forceinline__ float ex2(float x) {
    float y; asm("ex2.approx.f32 %0, %1;" : "=f"(y) : "f"(x)); return y;
}
__device__ __forceinline__ uint32_t smem_u32(const void* p) {
    uint32_t a;
    asm("{ .reg .u64 t; cvta.to.shared.u64 t, %1; cvt.u32.u64 %0, t; }" : "=r"(a) : "l"(p));
    return a;
}
__device__ __forceinline__ void split_pair(float x, float y, uint32_t& hi, uint32_t& lo) {
    __nv_bfloat162 hp = __floats2bfloat162_rn(x, y);
    float rx = x - __bfloat162float(hp.x);
    float ry = y - __bfloat162float(hp.y);
    __nv_bfloat162 lp2 = __floats2bfloat162_rn(rx, ry);
    hi = *(uint32_t*)&hp; lo = *(uint32_t*)&lp2;
}

#define LDSM4(r, a) \
    asm volatile("ldmatrix.sync.aligned.m8n8.x4.shared.b16 {%0,%1,%2,%3}, [%4];" \
        : "=r"((r)[0]), "=r"((r)[1]), "=r"((r)[2]), "=r"((r)[3]) : "r"(a))
#define LDSM2(r, a) \
    asm volatile("ldmatrix.sync.aligned.m8n8.x2.shared.b16 {%0,%1}, [%2];" \
        : "=r"((r)[0]), "=r"((r)[1]) : "r"(a))
#define LDSM2T(r, a) \
    asm volatile("ldmatrix.sync.aligned.m8n8.x2.trans.shared.b16 {%0,%1}, [%2];" \
        : "=r"((r)[0]), "=r"((r)[1]) : "r"(a))
#define MMA16816(d, a, b) \
    asm volatile("mma.sync.aligned.m16n8k16.row.col.f32.bf16.bf16.f32 " \
        "{%0,%1,%2,%3}, {%4,%5,%6,%7}, {%8,%9}, {%0,%1,%2,%3};" \
        : "+f"((d)[0]), "+f"((d)[1]), "+f"((d)[2]), "+f"((d)[3]) \
        : "r"((a)[0]), "r"((a)[1]), "r"((a)[2]), "r"((a)[3]), "r"((b)[0]), "r"((b)[1]))
#define CP_ASYNC16(dst, src) \
    asm volatile("cp.async.ca.shared.global [%0], [%1], 16;" :: "r"(dst), "l"(src))
#define CP_COMMIT() asm volatile("cp.async.commit_group;")
#define CP_WAIT(n)  asm volatile("cp.async.wait_group %0;" :: "n"(n))

// ---------------------------------------------------------------------------
// fp32 -> bf16 hi/lo split
// ---------------------------------------------------------------------------
__global__ __launch_bounds__(256)
void conv_split(const float* __restrict__ x, __nv_bfloat16* __restrict__ hi,
                __nv_bfloat16* __restrict__ lo)
{
    size_t i = ((size_t)blockIdx.x * 256 + threadIdx.x) * 4;
    float4 v = *(const float4*)&x[i];
    uint32_t h0, l0, h1, l1;
    split_pair(v.x, v.y, h0, l0);
    split_pair(v.z, v.w, h1, l1);
    *(uint2*)&hi[i] = make_uint2(h0, h1);
    *(uint2*)&lo[i] = make_uint2(l0, l1);
}

// ---------------------------------------------------------------------------
// Mask bit-pack
// ---------------------------------------------------------------------------
__global__ __launch_bounds__(256)
void pack_mask(const int* __restrict__ m)
{
    size_t i = (size_t)blockIdx.x * 256 + threadIdx.x;
    unsigned bit = (m[i] != 0) ? 1u : 0u;
    unsigned w = __ballot_sync(0xffffffff, bit);
    if ((threadIdx.x & 31) == 0) g_mbits[i >> 5] = w;
}

// ---------------------------------------------------------------------------
// bf16x3 HMMA GEMM with 3-stage cp.async pipeline.
// Block 128x128, K-chunk 16 (64 chunks), 256 threads = 8 warps (2m x 4n).
// Smem: 3 stages x 4 tiles x [128][16] bf16 = exactly 48KB, XOR-swizzled.
// ---------------------------------------------------------------------------
#define NST 3
#define NCHUNKS (DMODEL / 16)   // 64

// byte offset of 16B chunk (row, ch) of tile t in stage s, with XOR swizzle
__device__ __forceinline__ uint32_t tile_off(int s, int t, int row, int ch) {
    return (uint32_t)(((((s * 4 + t) * 128 + row) << 4) +
                       ((ch ^ ((row >> 2) & 1)) << 3)) << 1);
}

template<int LAYOUT>
__global__ __launch_bounds__(256)
void gemm_mma(const __nv_bfloat16* __restrict__ Ah, const __nv_bfloat16* __restrict__ Al,
              const __nv_bfloat16* __restrict__ Wh, const __nv_bfloat16* __restrict__ Wl,
              const float* __restrict__ bias, float* __restrict__ C,
              __nv_bfloat16* __restrict__ Chi, __nv_bfloat16* __restrict__ Clo,
              float scale)
{
    __shared__ __align__(16) __nv_bfloat16 sm[NST * 4 * 128 * 16];   // 49152 B

    const int tid  = threadIdx.x;
    const int lane = tid & 31;
    const int w    = tid >> 5;
    const int wm   = (w >> 2) * 64;
    const int wn   = (w & 3) * 32;
    const int n0 = blockIdx.x * 128;
    const int m0 = blockIdx.y * 128;
    const uint32_t sb = smem_u32(sm);

    const __nv_bfloat16* srcs[4] = {
        Ah + (size_t)m0 * DMODEL, Al + (size_t)m0 * DMODEL,
        Wh + (size_t)n0 * DMODEL, Wl + (size_t)n0 * DMODEL };

    const int lrow = tid >> 1;
    const int lch  = tid & 1;
    const size_t lgof = (size_t)lrow * DMODEL + lch * 8;

    float acc[4][4][4];
    #pragma unroll
    for (int mt = 0; mt < 4; mt++)
        #pragma unroll
        for (int nt = 0; nt < 4; nt++)
            #pragma unroll
            for (int e = 0; e < 4; e++) acc[mt][nt][e] = 0.f;

    // prologue: stages for chunks 0 and 1
    #pragma unroll
    for (int c = 0; c < NST - 1; c++) {
        #pragma unroll
        for (int t = 0; t < 4; t++)
            CP_ASYNC16(sb + tile_off(c, t, lrow, lch), srcs[t] + lgof + c * 16);
        CP_COMMIT();
    }

    const int a_row = lane & 15;
    const int a_ch  = lane >> 4;

    for (int c = 0; c < NCHUNKS; c++) {
        const int s = c % NST;
        CP_WAIT(1);
        __syncthreads();

        uint32_t ah[4][4], al[4][4];
        #pragma unroll
        for (int mt = 0; mt < 4; mt++) {
            LDSM4(ah[mt], sb + tile_off(s, 0, wm + mt * 16 + a_row, a_ch));
            LDSM4(al[mt], sb + tile_off(s, 1, wm + mt * 16 + a_row, a_ch));
        }
        uint32_t b4h[2][4], b4l[2][4];
        #pragma unroll
        for (int p = 0; p < 2; p++) {
            LDSM4(b4h[p], sb + tile_off(s, 2, wn + p * 16 + a_row, a_ch));
            LDSM4(b4l[p], sb + tile_off(s, 3, wn + p * 16 + a_row, a_ch));
        }
        uint32_t bh[4][2], bl[4][2];
        #pragma unroll
        for (int p = 0; p < 2; p++) {
            bh[2*p][0]   = b4h[p][0]; bh[2*p][1]   = b4h[p][2];
            bh[2*p+1][0] = b4h[p][1]; bh[2*p+1][1] = b4h[p][3];
            bl[2*p][0]   = b4l[p][0]; bl[2*p][1]   = b4l[p][2];
            bl[2*p+1][0] = b4l[p][1]; bl[2*p+1][1] = b4l[p][3];
        }
        #pragma unroll
        for (int mt = 0; mt < 4; mt++)
            #pragma unroll
            for (int nt = 0; nt < 4; nt++) {
                MMA16816(acc[mt][nt], ah[mt], bh[nt]);
                MMA16816(acc[mt][nt], ah[mt], bl[nt]);
                MMA16816(acc[mt][nt], al[mt], bh[nt]);
            }
        __syncthreads();

        const int cn = c + NST - 1;
        if (cn < NCHUNKS) {
            #pragma unroll
            for (int t = 0; t < 4; t++)
                CP_ASYNC16(sb + tile_off(cn % NST, t, lrow, lch), srcs[t] + lgof + cn * 16);
        }
        CP_COMMIT();
    }

    const int er = lane >> 2;
    const int ec = (lane & 3) * 2;
    #pragma unroll
    for (int mt = 0; mt < 4; mt++) {
        #pragma unroll
        for (int half = 0; half < 2; half++) {
            int m = m0 + wm + mt * 16 + er + half * 8;
            #pragma unroll
            for (int nt = 0; nt < 4; nt++) {
                int n = n0 + wn + nt * 8 + ec;
                float f0 = (acc[mt][nt][half * 2 + 0] + __ldg(&bias[n]))     * scale;
                float f1 = (acc[mt][nt][half * 2 + 1] + __ldg(&bias[n + 1])) * scale;
                if (LAYOUT == 0) {
                    *(u64*)&C[(size_t)m * DMODEL + n] = pack2(f0, f1);
                } else {
                    int b  = m >> 11;
                    int sq = m & (SS - 1);
                    int hh = n >> 6;
                    int dk = n & (DK - 1);
                    size_t o = ((((size_t)b * H + hh) * SS + sq) * DK) + dk;
                    uint32_t hi, lo;
                    split_pair(f0, f1, hi, lo);
                    *(uint32_t*)&Chi[o] = hi;
                    *(uint32_t*)&Clo[o] = lo;
                }
            }
        }
    }
}

// ---------------------------------------------------------------------------
// HMMA flash attention (bf16x3) — unchanged (passing)
// ---------------------------------------------------------------------------
__global__ __launch_bounds__(128)
void attn_mma()
{
    __shared__ __nv_bfloat16 sQh[64][72], sQl[64][72];
    __shared__ __nv_bfloat16 sKh[32][72], sKl[32][72];
    __shared__ __nv_bfloat16 sVh[32][72], sVl[32][72];

    const int tid  = threadIdx.x;
    const int lane = tid & 31;
    const int w    = tid >> 5;
    const int wq   = w * 16;
    const int q0 = blockIdx.x * 64;
    const int h  = blockIdx.y;
    const int bz = blockIdx.z;

    const size_t hb = ((size_t)bz * H + h) * SS;
    const __nv_bfloat16* gqh = g_qh + (hb + q0) * DK;
    const __nv_bfloat16* gql = g_ql + (hb + q0) * DK;
    const __nv_bfloat16* gkh = g_kh + hb * DK;
    const __nv_bfloat16* gkl = g_kl + hb * DK;
    const __nv_bfloat16* gvh = g_vh + hb * DK;
    const __nv_bfloat16* gvl = g_vl + hb * DK;

    #pragma unroll
    for (int i = 0; i < 4; i++) {
        int idx = tid + i * 128;
        int row = idx >> 3, c8 = idx & 7;
        *(uint4*)&sQh[row][c8 * 8] = *(const uint4*)(gqh + (size_t)row * DK + c8 * 8);
        *(uint4*)&sQl[row][c8 * 8] = *(const uint4*)(gql + (size_t)row * DK + c8 * 8);
    }

    float acc[8][4];
    #pragma unroll
    for (int nt = 0; nt < 8; nt++)
        #pragma unroll
        for (int e = 0; e < 4; e++) acc[nt][e] = 0.f;
    float mrun0 = -1e30f, mrun1 = -1e30f;
    float lp0 = 0.f, lp1 = 0.f;

    const int er = lane >> 2, ec = (lane & 3) * 2;
    const int a_row = lane & 15, a_kof = (lane >> 4) * 8;
    const int l16 = lane & 15;
    const int b_row = l16 & 7, b_kof = (l16 >> 3) * 8;

    const size_t mrow0 = ((size_t)bz * SS + q0 + wq + er) * (SS / 32);
    const size_t mrow1 = mrow0 + 8 * (SS / 32);

    for (int t = 0; t < SS / 32; t++) {
        const int k0 = t * 32;
        __syncthreads();
        #pragma unroll
        for (int i = 0; i < 2; i++) {
            int idx = tid + i * 128;
            int row = idx >> 3, c8 = idx & 7;
            size_t go = (size_t)(k0 + row) * DK + c8 * 8;
            *(uint4*)&sKh[row][c8 * 8] = *(const uint4*)(gkh + go);
            *(uint4*)&sKl[row][c8 * 8] = *(const uint4*)(gkl + go);
            *(uint4*)&sVh[row][c8 * 8] = *(const uint4*)(gvh + go);
            *(uint4*)&sVl[row][c8 * 8] = *(const uint4*)(gvl + go);
        }
        __syncthreads();

        float sc[4][4];
        #pragma unroll
        for (int nt = 0; nt < 4; nt++)
            #pragma unroll
            for (int e = 0; e < 4; e++) sc[nt][e] = 0.f;

        #pragma unroll
        for (int ks = 0; ks < 4; ks++) {
            uint32_t ah[4], al[4];
            LDSM4(ah, smem_u32(&sQh[wq + a_row][ks * 16 + a_kof]));
            LDSM4(al, smem_u32(&sQl[wq + a_row][ks * 16 + a_kof]));
            #pragma unroll
            for (int nt = 0; nt < 4; nt++) {
                uint32_t bh[2], bl[2];
                LDSM2(bh, smem_u32(&sKh[nt * 8 + b_row][ks * 16 + b_kof]));
                LDSM2(bl, smem_u32(&sKl[nt * 8 + b_row][ks * 16 + b_kof]));
                MMA16816(sc[nt], ah, bh);
                MMA16816(sc[nt], ah, bl);
                MMA16816(sc[nt], al, bh);
            }
        }

        unsigned mw0 = g_mbits[mrow0 + t];
        unsigned mw1 = g_mbits[mrow1 + t];
        #pragma unroll
        for (int nt = 0; nt < 4; nt++) {
            int j0 = nt * 8 + ec;
            if (!((mw0 >> j0) & 1u))       sc[nt][0] = MASKVAL;
            if (!((mw0 >> (j0 + 1)) & 1u)) sc[nt][1] = MASKVAL;
            if (!((mw1 >> j0) & 1u))       sc[nt][2] = MASKVAL;
            if (!((mw1 >> (j0 + 1)) & 1u)) sc[nt][3] = MASKVAL;
        }
        float m0 = mrun0, m1 = mrun1;
        #pragma unroll
        for (int nt = 0; nt < 4; nt++) {
            m0 = fmaxf(m0, fmaxf(sc[nt][0], sc[nt][1]));
            m1 = fmaxf(m1, fmaxf(sc[nt][2], sc[nt][3]));
        }
        m0 = fmaxf(m0, __shfl_xor_sync(0xffffffff, m0, 1));
        m0 = fmaxf(m0, __shfl_xor_sync(0xffffffff, m0, 2));
        m1 = fmaxf(m1, __shfl_xor_sync(0xffffffff, m1, 1));
        m1 = fmaxf(m1, __shfl_xor_sync(0xffffffff, m1, 2));
        float al0 = ex2(mrun0 - m0);
        float al1 = ex2(mrun1 - m1);
        mrun0 = m0; mrun1 = m1;
        lp0 *= al0; lp1 *= al1;
        #pragma unroll
        for (int nt = 0; nt < 8; nt++) {
            acc[nt][0] *= al0; acc[nt][1] *= al0;
            acc[nt][2] *= al1; acc[nt][3] *= al1;
        }
        float s0 = 0.f, s1 = 0.f;
        #pragma unroll
        for (int nt = 0; nt < 4; nt++) {
            sc[nt][0] = ex2(sc[nt][0] - m0); s0 += sc[nt][0];
            sc[nt][1] = ex2(sc[nt][1] - m0); s0 += sc[nt][1];
            sc[nt][2] = ex2(sc[nt][2] - m1); s1 += sc[nt][2];
            sc[nt][3] = ex2(sc[nt][3] - m1); s1 += sc[nt][3];
        }
        lp0 += s0; lp1 += s1;

        #pragma unroll
        for (int t2 = 0; t2 < 2; t2++) {
            uint32_t ph[4], pl[4];
            split_pair(sc[2*t2][0],   sc[2*t2][1],   ph[0], pl[0]);
            split_pair(sc[2*t2][2],   sc[2*t2][3],   ph[1], pl[1]);
            split_pair(sc[2*t2+1][0], sc[2*t2+1][1], ph[2], pl[2]);
            split_pair(sc[2*t2+1][2], sc[2*t2+1][3], ph[3], pl[3]);
            #pragma unroll
            for (int nt = 0; nt < 8; nt++) {
                uint32_t vh[2], vl[2];
                LDSM2T(vh, smem_u32(&sVh[t2 * 16 + l16][nt * 8]));
                LDSM2T(vl, smem_u32(&sVl[t2 * 16 + l16][nt * 8]));
                MMA16816(acc[nt], ph, vh);
                MMA16816(acc[nt], ph, vl);
                MMA16816(acc[nt], pl, vh);
            }
        }
    }

    lp0 += __shfl_xor_sync(0xffffffff, lp0, 1);
    lp0 += __shfl_xor_sync(0xffffffff, lp0, 2);
    lp1 += __shfl_xor_sync(0xffffffff, lp1, 1);
    lp1 += __shfl_xor_sync(0xffffffff, lp1, 2);
    float inv0 = 1.0f / lp0;
    float inv1 = 1.0f / lp1;

    size_t ro0 = ((size_t)bz * SS + q0 + wq + er) * DMODEL + (size_t)h * DK;
    size_t ro1 = ro0 + 8 * DMODEL;
    #pragma unroll
    for (int nt = 0; nt < 8; nt++) {
        int c = nt * 8 + ec;
        uint32_t hi, lo;
        split_pair(acc[nt][0] * inv0, acc[nt][1] * inv0, hi, lo);
        *(uint32_t*)&g_inh[ro0 + c] = hi;
        *(uint32_t*)&g_inl[ro0 + c] = lo;
        split_pair(acc[nt][2] * inv1, acc[nt][3] * inv1, hi, lo);
        *(uint32_t*)&g_inh[ro1 + c] = hi;
        *(uint32_t*)&g_inl[ro1 + c] = lo;
    }
}

// ---------------------------------------------------------------------------
extern "C" void kernel_launch(void* const* d_in, const int* in_sizes, int n_in,
                              void* d_out, int out_size)
{
    const float* q    = (const float*)d_in[0];
    const float* k    = (const float*)d_in[1];
    const float* v    = (const float*)d_in[2];
    const int*   mask = (const int*)  d_in[3];
    const float* Wq   = (const float*)d_in[4];
    const float* bq   = (const float*)d_in[5];
    const float* Wk   = (const float*)d_in[6];
    const float* bk   = (const float*)d_in[7];
    const float* Wv   = (const float*)d_in[8];
    const float* bv   = (const float*)d_in[9];
    const float* Wo   = (const float*)d_in[10];
    const float* bo   = (const float*)d_in[11];
    float* out = (float*)d_out;

    __nv_bfloat16 *ih, *il, *wh, *wl, *qh, *ql, *kh, *kl, *vh, *vl;
    cudaGetSymbolAddress((void**)&ih, g_inh);
    cudaGetSymbolAddress((void**)&il, g_inl);
    cudaGetSymbolAddress((void**)&wh, g_wh);
    cudaGetSymbolAddress((void**)&wl, g_wl);
    cudaGetSymbolAddress((void**)&qh, g_qh);
    cudaGetSymbolAddress((void**)&ql, g_ql);
    cudaGetSymbolAddress((void**)&kh, g_kh);
    cudaGetSymbolAddress((void**)&kl, g_kl);
    cudaGetSymbolAddress((void**)&vh, g_vh);
    cudaGetSymbolAddress((void**)&vl, g_vl);

    const int ACT_BLKS = (M_ROWS * DMODEL) / (256 * 4);   // 4096
    const int W_BLKS   = (DMODEL * DMODEL) / (256 * 4);   // 1024
    dim3 gg(DMODEL / 128, M_ROWS / 128);                   // (8, 32)

    pack_mask<<<(size_t)BB * SS * SS / 256, 256>>>(mask);

    conv_split<<<ACT_BLKS, 256>>>(q, ih, il);
    conv_split<<<W_BLKS, 256>>>(Wq, wh, wl);
    gemm_mma<1><<<gg, 256>>>(ih, il, wh, wl, bq, nullptr, qh, ql, QSCALE);

    conv_split<<<ACT_BLKS, 256>>>(k, ih, il);
    conv_split<<<W_BLKS, 256>>>(Wk, wh, wl);
    gemm_mma<1><<<gg, 256>>>(ih, il, wh, wl, bk, nullptr, kh, kl, 1.0f);

    conv_split<<<ACT_BLKS, 256>>>(v, ih, il);
    conv_split<<<W_BLKS, 256>>>(Wv, wh, wl);
    gemm_mma<1><<<gg, 256>>>(ih, il, wh, wl, bv, nullptr, vh, vl, 1.0f);

    attn_mma<<<dim3(SS / 64, H, BB), 128>>>();

    conv_split<<<W_BLKS, 256>>>(Wo, wh, wl);
    gemm_mma<0><<<gg, 256>>>(ih, il, wh, wl, bo, out, nullptr, nullptr, 1.0f);
}

// round 10
// speedup vs baseline: 3.4629x; 1.0857x over previous
#include <cuda_runtime.h>
#include <cuda_bf16.h>
#include <cstdint>
#include <cstddef>

#define H 16
#define DMODEL 1024
#define DK 64
#define BB 2
#define SS 2048
#define M_ROWS (BB*SS)   // 4096

typedef unsigned long long u64;

// Scratch (device globals — no allocation allowed)
__device__ unsigned int g_mbits[(size_t)BB*SS*(SS/32)];
__device__ __nv_bfloat16 g_qh[(size_t)BB*H*SS*DK];
__device__ __nv_bfloat16 g_ql[(size_t)BB*H*SS*DK];
__device__ __nv_bfloat16 g_kh[(size_t)BB*H*SS*DK];
__device__ __nv_bfloat16 g_kl[(size_t)BB*H*SS*DK];
__device__ __nv_bfloat16 g_vh[(size_t)BB*H*SS*DK];
__device__ __nv_bfloat16 g_vl[(size_t)BB*H*SS*DK];
__device__ __nv_bfloat16 g_inh[(size_t)M_ROWS*DMODEL];
__device__ __nv_bfloat16 g_inl[(size_t)M_ROWS*DMODEL];
__device__ __nv_bfloat16 g_wh[(size_t)DMODEL*DMODEL];
__device__ __nv_bfloat16 g_wl[(size_t)DMODEL*DMODEL];

#define QSCALE 0.18033688011112042f   /* (1/8) * log2(e) */
#define MASKVAL (-14427.0f)           /* -10000 * log2(e)  */

// ---------------------------------------------------------------------------
// helpers
// ---------------------------------------------------------------------------
__device__ __forceinline__ u64 pack2(float x, float y) {
    u64 d; asm("mov.b64 %0, {%1, %2};" : "=l"(d) : "f"(x), "f"(y)); return d;
}
__device__ __forceinline__ float ex2(float x) {
    float y; asm("ex2.approx.f32 %0, %1;" : "=f"(y) : "f"(x)); return y;
}
__device__ __forceinline__ uint32_t smem_u32(const void* p) {
    uint32_t a;
    asm("{ .reg .u64 t; cvta.to.shared.u64 t, %1; cvt.u32.u64 %0, t; }" : "=r"(a) : "l"(p));
    return a;
}
__device__ __forceinline__ void split_pair(float x, float y, uint32_t& hi, uint32_t& lo) {
    __nv_bfloat162 hp = __floats2bfloat162_rn(x, y);
    float rx = x - __bfloat162float(hp.x);
    float ry = y - __bfloat162float(hp.y);
    __nv_bfloat162 lp2 = __floats2bfloat162_rn(rx, ry);
    hi = *(uint32_t*)&hp; lo = *(uint32_t*)&lp2;
}

#define LDSM4(r, a) \
    asm volatile("ldmatrix.sync.aligned.m8n8.x4.shared.b16 {%0,%1,%2,%3}, [%4];" \
        : "=r"((r)[0]), "=r"((r)[1]), "=r"((r)[2]), "=r"((r)[3]) : "r"(a))
#define LDSM4T(r, a) \
    asm volatile("ldmatrix.sync.aligned.m8n8.x4.trans.shared.b16 {%0,%1,%2,%3}, [%4];" \
        : "=r"((r)[0]), "=r"((r)[1]), "=r"((r)[2]), "=r"((r)[3]) : "r"(a))
#define MMA16816(d, a, b) \
    asm volatile("mma.sync.aligned.m16n8k16.row.col.f32.bf16.bf16.f32 " \
        "{%0,%1,%2,%3}, {%4,%5,%6,%7}, {%8,%9}, {%0,%1,%2,%3};" \
        : "+f"((d)[0]), "+f"((d)[1]), "+f"((d)[2]), "+f"((d)[3]) \
        : "r"((a)[0]), "r"((a)[1]), "r"((a)[2]), "r"((a)[3]), "r"((b)[0]), "r"((b)[1]))
#define CP_ASYNC16(dst, src) \
    asm volatile("cp.async.ca.shared.global [%0], [%1], 16;" :: "r"(dst), "l"(src))
#define CP_COMMIT() asm volatile("cp.async.commit_group;")
#define CP_WAIT(n)  asm volatile("cp.async.wait_group %0;" :: "n"(n))

// ---------------------------------------------------------------------------
// fp32 -> bf16 hi/lo split
// ---------------------------------------------------------------------------
__global__ __launch_bounds__(256)
void conv_split(const float* __restrict__ x, __nv_bfloat16* __restrict__ hi,
                __nv_bfloat16* __restrict__ lo)
{
    size_t i = ((size_t)blockIdx.x * 256 + threadIdx.x) * 4;
    float4 v = *(const float4*)&x[i];
    uint32_t h0, l0, h1, l1;
    split_pair(v.x, v.y, h0, l0);
    split_pair(v.z, v.w, h1, l1);
    *(uint2*)&hi[i] = make_uint2(h0, h1);
    *(uint2*)&lo[i] = make_uint2(l0, l1);
}

// ---------------------------------------------------------------------------
// Mask bit-pack
// ---------------------------------------------------------------------------
__global__ __launch_bounds__(256)
void pack_mask(const int* __restrict__ m)
{
    size_t i = (size_t)blockIdx.x * 256 + threadIdx.x;
    unsigned bit = (m[i] != 0) ? 1u : 0u;
    unsigned w = __ballot_sync(0xffffffff, bit);
    if ((threadIdx.x & 31) == 0) g_mbits[i >> 5] = w;
}

// ---------------------------------------------------------------------------
// bf16x3 HMMA GEMM, 3-stage cp.async pipeline, ONE sync per chunk.
// Block 128x128, K-chunk 16 (64 chunks), 256 threads = 8 warps (2m x 4n).
// ---------------------------------------------------------------------------
#define NST 3
#define NCHUNKS (DMODEL / 16)   // 64

__device__ __forceinline__ uint32_t tile_off(int s, int t, int row, int ch) {
    return (uint32_t)(((((s * 4 + t) * 128 + row) << 4) +
                       ((ch ^ ((row >> 2) & 1)) << 3)) << 1);
}

template<int LAYOUT>
__global__ __launch_bounds__(256)
void gemm_mma(const __nv_bfloat16* __restrict__ Ah, const __nv_bfloat16* __restrict__ Al,
              const __nv_bfloat16* __restrict__ Wh, const __nv_bfloat16* __restrict__ Wl,
              const float* __restrict__ bias, float* __restrict__ C,
              __nv_bfloat16* __restrict__ Chi, __nv_bfloat16* __restrict__ Clo,
              float scale)
{
    __shared__ __align__(16) __nv_bfloat16 sm[NST * 4 * 128 * 16];   // 49152 B

    const int tid  = threadIdx.x;
    const int lane = tid & 31;
    const int w    = tid >> 5;
    const int wm   = (w >> 2) * 64;
    const int wn   = (w & 3) * 32;
    const int n0 = blockIdx.x * 128;
    const int m0 = blockIdx.y * 128;
    const uint32_t sb = smem_u32(sm);

    const __nv_bfloat16* srcs[4] = {
        Ah + (size_t)m0 * DMODEL, Al + (size_t)m0 * DMODEL,
        Wh + (size_t)n0 * DMODEL, Wl + (size_t)n0 * DMODEL };

    const int lrow = tid >> 1;
    const int lch  = tid & 1;
    const size_t lgof = (size_t)lrow * DMODEL + lch * 8;

    float acc[4][4][4];
    #pragma unroll
    for (int mt = 0; mt < 4; mt++)
        #pragma unroll
        for (int nt = 0; nt < 4; nt++)
            #pragma unroll
            for (int e = 0; e < 4; e++) acc[mt][nt][e] = 0.f;

    #pragma unroll
    for (int c = 0; c < NST - 1; c++) {
        #pragma unroll
        for (int t = 0; t < 4; t++)
            CP_ASYNC16(sb + tile_off(c, t, lrow, lch), srcs[t] + lgof + c * 16);
        CP_COMMIT();
    }

    const int a_row = lane & 15;
    const int a_ch  = lane >> 4;

    for (int c = 0; c < NCHUNKS; c++) {
        const int s = c % NST;
        CP_WAIT(1);
        __syncthreads();

        // issue chunk c+2 NOW (stage (c+2)%NST was last read at chunk c-1;
        // the sync above proves all warps are past it), then compute chunk c.
        const int cn = c + NST - 1;
        if (cn < NCHUNKS) {
            #pragma unroll
            for (int t = 0; t < 4; t++)
                CP_ASYNC16(sb + tile_off(cn % NST, t, lrow, lch), srcs[t] + lgof + cn * 16);
        }
        CP_COMMIT();

        uint32_t ah[4][4], al[4][4];
        #pragma unroll
        for (int mt = 0; mt < 4; mt++) {
            LDSM4(ah[mt], sb + tile_off(s, 0, wm + mt * 16 + a_row, a_ch));
            LDSM4(al[mt], sb + tile_off(s, 1, wm + mt * 16 + a_row, a_ch));
        }
        uint32_t b4h[2][4], b4l[2][4];
        #pragma unroll
        for (int p = 0; p < 2; p++) {
            LDSM4(b4h[p], sb + tile_off(s, 2, wn + p * 16 + a_row, a_ch));
            LDSM4(b4l[p], sb + tile_off(s, 3, wn + p * 16 + a_row, a_ch));
        }
        uint32_t bh[4][2], bl[4][2];
        #pragma unroll
        for (int p = 0; p < 2; p++) {
            bh[2*p][0]   = b4h[p][0]; bh[2*p][1]   = b4h[p][2];
            bh[2*p+1][0] = b4h[p][1]; bh[2*p+1][1] = b4h[p][3];
            bl[2*p][0]   = b4l[p][0]; bl[2*p][1]   = b4l[p][2];
            bl[2*p+1][0] = b4l[p][1]; bl[2*p+1][1] = b4l[p][3];
        }
        #pragma unroll
        for (int mt = 0; mt < 4; mt++)
            #pragma unroll
            for (int nt = 0; nt < 4; nt++) {
                MMA16816(acc[mt][nt], ah[mt], bh[nt]);
                MMA16816(acc[mt][nt], ah[mt], bl[nt]);
                MMA16816(acc[mt][nt], al[mt], bh[nt]);
            }
    }

    const int er = lane >> 2;
    const int ec = (lane & 3) * 2;
    #pragma unroll
    for (int mt = 0; mt < 4; mt++) {
        #pragma unroll
        for (int half = 0; half < 2; half++) {
            int m = m0 + wm + mt * 16 + er + half * 8;
            #pragma unroll
            for (int nt = 0; nt < 4; nt++) {
                int n = n0 + wn + nt * 8 + ec;
                float f0 = (acc[mt][nt][half * 2 + 0] + __ldg(&bias[n]))     * scale;
                float f1 = (acc[mt][nt][half * 2 + 1] + __ldg(&bias[n + 1])) * scale;
                if (LAYOUT == 0) {
                    *(u64*)&C[(size_t)m * DMODEL + n] = pack2(f0, f1);
                } else {
                    int b  = m >> 11;
                    int sq = m & (SS - 1);
                    int hh = n >> 6;
                    int dk = n & (DK - 1);
                    size_t o = ((((size_t)b * H + hh) * SS + sq) * DK) + dk;
                    uint32_t hi, lo;
                    split_pair(f0, f1, hi, lo);
                    *(uint32_t*)&Chi[o] = hi;
                    *(uint32_t*)&Clo[o] = lo;
                }
            }
        }
    }
}

// ---------------------------------------------------------------------------
// HMMA flash attention (bf16x3), Q fragments in registers,
// 2-stage cp.async K/V pipeline, SW128-swizzled tiles (32 rows x 64 bf16).
// Block = 64 q-rows x one (b,h), 128 threads, 4 warps x 16q x 32keys.
// ---------------------------------------------------------------------------
// byte offset within sKV: stage s (0/1), tile t (Kh,Kl,Vh,Vl), row 0..31, 16B chunk 0..7
__device__ __forceinline__ uint32_t kv_off(int s, int t, int row, int ch) {
    return (uint32_t)((((s * 4 + t) * 32 + row) * 128) + ((ch ^ (row & 7)) * 16));
}

__global__ __launch_bounds__(128)
void attn_mma()
{
    __shared__ __align__(16) char sKV[32768];   // 2 stages x 4 tiles x 4KB

    const int tid  = threadIdx.x;
    const int lane = tid & 31;
    const int w    = tid >> 5;
    const int wq   = w * 16;
    const int q0 = blockIdx.x * 64;
    const int h  = blockIdx.y;
    const int bz = blockIdx.z;
    const uint32_t sb = smem_u32(sKV);

    const size_t hb = ((size_t)bz * H + h) * SS;
    const __nv_bfloat16* gqh = g_qh + (hb + q0) * DK;
    const __nv_bfloat16* gql = g_ql + (hb + q0) * DK;
    const __nv_bfloat16* kvsrc[4] = {
        g_kh + hb * DK, g_kl + hb * DK, g_vh + hb * DK, g_vl + hb * DK };

    // ---- stage Q (64x64 hi+lo) through stage-0 smem, swizzled ----
    #pragma unroll
    for (int i = 0; i < 8; i++) {
        int idx = tid + i * 128;            // 0..1023
        int arr = idx >> 9;                 // 0 = hi, 1 = lo
        int rem = idx & 511;
        int row = rem >> 3, ch = rem & 7;
        const __nv_bfloat16* src = (arr ? gql : gqh) + (size_t)row * DK + ch * 8;
        *(uint4*)(sKV + kv_off(0, arr * 2 + (row >> 5), row & 31, ch)) = *(const uint4*)src;
    }
    __syncthreads();

    // ---- extract Q fragments to registers (reused all 64 iterations) ----
    uint32_t qfh[4][4], qfl[4][4];
    {
        const int a_row = lane & 15, a_ch = lane >> 4;
        const int r = wq + a_row, lr = r & 31, ts = r >> 5;
        #pragma unroll
        for (int ks = 0; ks < 4; ks++) {
            LDSM4(qfh[ks], sb + kv_off(0, ts, lr, ks * 2 + a_ch));
            LDSM4(qfl[ks], sb + kv_off(0, 2 + ts, lr, ks * 2 + a_ch));
        }
    }
    __syncthreads();

    float acc[8][4];
    #pragma unroll
    for (int nt = 0; nt < 8; nt++)
        #pragma unroll
        for (int e = 0; e < 4; e++) acc[nt][e] = 0.f;
    float mrun0 = -1e30f, mrun1 = -1e30f;
    float lp0 = 0.f, lp1 = 0.f;

    const int er = lane >> 2, ec = (lane & 3) * 2;
    const size_t mrow0 = ((size_t)bz * SS + q0 + wq + er) * (SS / 32);
    const size_t mrow1 = mrow0 + 8 * (SS / 32);

    // ---- prologue: issue K/V tile 0 ----
    #pragma unroll
    for (int i = 0; i < 8; i++) {
        int idx = tid + i * 128;
        int t = idx >> 8, rem = idx & 255, row = rem >> 3, ch = rem & 7;
        CP_ASYNC16(sb + kv_off(0, t, row, ch), kvsrc[t] + (size_t)row * DK + ch * 8);
    }
    CP_COMMIT();

    for (int it = 0; it < SS / 32; it++) {
        const int st = it & 1;
        CP_WAIT(0);
        __syncthreads();

        if (it + 1 < SS / 32) {
            const int k0n = (it + 1) * 32;
            #pragma unroll
            for (int i = 0; i < 8; i++) {
                int idx = tid + i * 128;
                int t = idx >> 8, rem = idx & 255, row = rem >> 3, ch = rem & 7;
                CP_ASYNC16(sb + kv_off(st ^ 1, t, row, ch),
                           kvsrc[t] + (size_t)(k0n + row) * DK + ch * 8);
            }
        }
        CP_COMMIT();

        // --- scores: 16q x 32k per warp ---
        float sc[4][4];
        #pragma unroll
        for (int nt = 0; nt < 4; nt++)
            #pragma unroll
            for (int e = 0; e < 4; e++) sc[nt][e] = 0.f;

        #pragma unroll
        for (int ks = 0; ks < 4; ks++) {
            uint32_t kc0h[4], kc1h[4], kc0l[4], kc1l[4];
            LDSM4(kc0h, sb + kv_off(st, 0, lane, ks * 2));
            LDSM4(kc1h, sb + kv_off(st, 0, lane, ks * 2 + 1));
            LDSM4(kc0l, sb + kv_off(st, 1, lane, ks * 2));
            LDSM4(kc1l, sb + kv_off(st, 1, lane, ks * 2 + 1));
            #pragma unroll
            for (int nt = 0; nt < 4; nt++) {
                uint32_t bh[2] = { kc0h[nt], kc1h[nt] };
                uint32_t bl[2] = { kc0l[nt], kc1l[nt] };
                MMA16816(sc[nt], qfh[ks], bh);
                MMA16816(sc[nt], qfh[ks], bl);
                MMA16816(sc[nt], qfl[ks], bh);
            }
        }

        // --- mask + online softmax ---
        unsigned mw0 = g_mbits[mrow0 + it];
        unsigned mw1 = g_mbits[mrow1 + it];
        #pragma unroll
        for (int nt = 0; nt < 4; nt++) {
            int j0 = nt * 8 + ec;
            if (!((mw0 >> j0) & 1u))       sc[nt][0] = MASKVAL;
            if (!((mw0 >> (j0 + 1)) & 1u)) sc[nt][1] = MASKVAL;
            if (!((mw1 >> j0) & 1u))       sc[nt][2] = MASKVAL;
            if (!((mw1 >> (j0 + 1)) & 1u)) sc[nt][3] = MASKVAL;
        }
        float m0 = mrun0, m1 = mrun1;
        #pragma unroll
        for (int nt = 0; nt < 4; nt++) {
            m0 = fmaxf(m0, fmaxf(sc[nt][0], sc[nt][1]));
            m1 = fmaxf(m1, fmaxf(sc[nt][2], sc[nt][3]));
        }
        m0 = fmaxf(m0, __shfl_xor_sync(0xffffffff, m0, 1));
        m0 = fmaxf(m0, __shfl_xor_sync(0xffffffff, m0, 2));
        m1 = fmaxf(m1, __shfl_xor_sync(0xffffffff, m1, 1));
        m1 = fmaxf(m1, __shfl_xor_sync(0xffffffff, m1, 2));
        float al0 = ex2(mrun0 - m0);
        float al1 = ex2(mrun1 - m1);
        mrun0 = m0; mrun1 = m1;
        lp0 *= al0; lp1 *= al1;
        #pragma unroll
        for (int nt = 0; nt < 8; nt++) {
            acc[nt][0] *= al0; acc[nt][1] *= al0;
            acc[nt][2] *= al1; acc[nt][3] *= al1;
        }
        float s0 = 0.f, s1 = 0.f;
        #pragma unroll
        for (int nt = 0; nt < 4; nt++) {
            sc[nt][0] = ex2(sc[nt][0] - m0); s0 += sc[nt][0];
            sc[nt][1] = ex2(sc[nt][1] - m0); s0 += sc[nt][1];
            sc[nt][2] = ex2(sc[nt][2] - m1); s1 += sc[nt][2];
            sc[nt][3] = ex2(sc[nt][3] - m1); s1 += sc[nt][3];
        }
        lp0 += s0; lp1 += s1;

        // --- PV: P fragments from score registers, V via ldmatrix.x4.trans ---
        #pragma unroll
        for (int t2 = 0; t2 < 2; t2++) {
            uint32_t ph[4], pl[4];
            split_pair(sc[2*t2][0],   sc[2*t2][1],   ph[0], pl[0]);
            split_pair(sc[2*t2][2],   sc[2*t2][3],   ph[1], pl[1]);
            split_pair(sc[2*t2+1][0], sc[2*t2+1][1], ph[2], pl[2]);
            split_pair(sc[2*t2+1][2], sc[2*t2+1][3], ph[3], pl[3]);
            const int vrow = t2 * 16 + (lane & 15);
            const int vch  = lane >> 4;
            #pragma unroll
            for (int p = 0; p < 4; p++) {
                uint32_t v4h[4], v4l[4];
                LDSM4T(v4h, sb + kv_off(st, 2, vrow, 2 * p + vch));
                LDSM4T(v4l, sb + kv_off(st, 3, vrow, 2 * p + vch));
                uint32_t vh0[2] = { v4h[0], v4h[1] }, vl0[2] = { v4l[0], v4l[1] };
                uint32_t vh1[2] = { v4h[2], v4h[3] }, vl1[2] = { v4l[2], v4l[3] };
                MMA16816(acc[2*p],   ph, vh0);
                MMA16816(acc[2*p],   ph, vl0);
                MMA16816(acc[2*p],   pl, vh0);
                MMA16816(acc[2*p+1], ph, vh1);
                MMA16816(acc[2*p+1], ph, vl1);
                MMA16816(acc[2*p+1], pl, vh1);
            }
        }
    }

    // --- finalize ---
    lp0 += __shfl_xor_sync(0xffffffff, lp0, 1);
    lp0 += __shfl_xor_sync(0xffffffff, lp0, 2);
    lp1 += __shfl_xor_sync(0xffffffff, lp1, 1);
    lp1 += __shfl_xor_sync(0xffffffff, lp1, 2);
    float inv0 = 1.0f / lp0;
    float inv1 = 1.0f / lp1;

    size_t ro0 = ((size_t)bz * SS + q0 + wq + er) * DMODEL + (size_t)h * DK;
    size_t ro1 = ro0 + 8 * DMODEL;
    #pragma unroll
    for (int nt = 0; nt < 8; nt++) {
        int c = nt * 8 + ec;
        uint32_t hi, lo;
        split_pair(acc[nt][0] * inv0, acc[nt][1] * inv0, hi, lo);
        *(uint32_t*)&g_inh[ro0 + c] = hi;
        *(uint32_t*)&g_inl[ro0 + c] = lo;
        split_pair(acc[nt][2] * inv1, acc[nt][3] * inv1, hi, lo);
        *(uint32_t*)&g_inh[ro1 + c] = hi;
        *(uint32_t*)&g_inl[ro1 + c] = lo;
    }
}

// ---------------------------------------------------------------------------
extern "C" void kernel_launch(void* const* d_in, const int* in_sizes, int n_in,
                              void* d_out, int out_size)
{
    const float* q    = (const float*)d_in[0];
    const float* k    = (const float*)d_in[1];
    const float* v    = (const float*)d_in[2];
    const int*   mask = (const int*)  d_in[3];
    const float* Wq   = (const float*)d_in[4];
    const float* bq   = (const float*)d_in[5];
    const float* Wk   = (const float*)d_in[6];
    const float* bk   = (const float*)d_in[7];
    const float* Wv   = (const float*)d_in[8];
    const float* bv   = (const float*)d_in[9];
    const float* Wo   = (const float*)d_in[10];
    const float* bo   = (const float*)d_in[11];
    float* out = (float*)d_out;

    __nv_bfloat16 *ih, *il, *wh, *wl, *qh, *ql, *kh, *kl, *vh, *vl;
    cudaGetSymbolAddress((void**)&ih, g_inh);
    cudaGetSymbolAddress((void**)&il, g_inl);
    cudaGetSymbolAddress((void**)&wh, g_wh);
    cudaGetSymbolAddress((void**)&wl, g_wl);
    cudaGetSymbolAddress((void**)&qh, g_qh);
    cudaGetSymbolAddress((void**)&ql, g_ql);
    cudaGetSymbolAddress((void**)&kh, g_kh);
    cudaGetSymbolAddress((void**)&kl, g_kl);
    cudaGetSymbolAddress((void**)&vh, g_vh);
    cudaGetSymbolAddress((void**)&vl, g_vl);

    const int ACT_BLKS = (M_ROWS * DMODEL) / (256 * 4);   // 4096
    const int W_BLKS   = (DMODEL * DMODEL) / (256 * 4);   // 1024
    dim3 gg(DMODEL / 128, M_ROWS / 128);                   // (8, 32)

    pack_mask<<<(size_t)BB * SS * SS / 256, 256>>>(mask);

    conv_split<<<ACT_BLKS, 256>>>(q, ih, il);
    conv_split<<<W_BLKS, 256>>>(Wq, wh, wl);
    gemm_mma<1><<<gg, 256>>>(ih, il, wh, wl, bq, nullptr, qh, ql, QSCALE);

    conv_split<<<ACT_BLKS, 256>>>(k, ih, il);
    conv_split<<<W_BLKS, 256>>>(Wk, wh, wl);
    gemm_mma<1><<<gg, 256>>>(ih, il, wh, wl, bk, nullptr, kh, kl, 1.0f);

    conv_split<<<ACT_BLKS, 256>>>(v, ih, il);
    conv_split<<<W_BLKS, 256>>>(Wv, wh, wl);
    gemm_mma<1><<<gg, 256>>>(ih, il, wh, wl, bv, nullptr, vh, vl, 1.0f);

    attn_mma<<<dim3(SS / 64, H, BB), 128>>>();

    conv_split<<<W_BLKS, 256>>>(Wo, wh, wl);
    gemm_mma<0><<<gg, 256>>>(ih, il, wh, wl, bo, out, nullptr, nullptr, 1.0f);
}

// round 11
// speedup vs baseline: 3.4728x; 1.0029x over previous
#include <cuda_runtime.h>
#include <cuda_bf16.h>
#include <cstdint>
#include <cstddef>

#define H 16
#define DMODEL 1024
#define DK 64
#define BB 2
#define SS 2048
#define M_ROWS (BB*SS)   // 4096

typedef unsigned long long u64;

// Scratch (device globals — no allocation allowed)
__device__ unsigned int g_mbits[(size_t)BB*SS*(SS/32)];
__device__ __nv_bfloat16 g_qh[(size_t)BB*H*SS*DK];
__device__ __nv_bfloat16 g_ql[(size_t)BB*H*SS*DK];
__device__ __nv_bfloat16 g_kh[(size_t)BB*H*SS*DK];
__device__ __nv_bfloat16 g_kl[(size_t)BB*H*SS*DK];
__device__ __nv_bfloat16 g_vh[(size_t)BB*H*SS*DK];
__device__ __nv_bfloat16 g_vl[(size_t)BB*H*SS*DK];
__device__ __nv_bfloat16 g_inh[(size_t)M_ROWS*DMODEL];
__device__ __nv_bfloat16 g_inl[(size_t)M_ROWS*DMODEL];
__device__ __nv_bfloat16 g_wh[(size_t)DMODEL*DMODEL];
__device__ __nv_bfloat16 g_wl[(size_t)DMODEL*DMODEL];

#define QSCALE 0.18033688011112042f   /* (1/8) * log2(e) */
#define MASKVAL (-14427.0f)           /* -10000 * log2(e)  */

// ---------------------------------------------------------------------------
// helpers
// ---------------------------------------------------------------------------
__device__ __forceinline__ u64 pack2(float x, float y) {
    u64 d; asm("mov.b64 %0, {%1, %2};" : "=l"(d) : "f"(x), "f"(y)); return d;
}
__device__ __forceinline__ float ex2(float x) {
    float y; asm("ex2.approx.f32 %0, %1;" : "=f"(y) : "f"(x)); return y;
}
__device__ __forceinline__ uint32_t smem_u32(const void* p) {
    uint32_t a;
    asm("{ .reg .u64 t; cvta.to.shared.u64 t, %1; cvt.u32.u64 %0, t; }" : "=r"(a) : "l"(p));
    return a;
}
__device__ __forceinline__ void split_pair(float x, float y, uint32_t& hi, uint32_t& lo) {
    __nv_bfloat162 hp = __floats2bfloat162_rn(x, y);
    float rx = x - __bfloat162float(hp.x);
    float ry = y - __bfloat162float(hp.y);
    __nv_bfloat162 lp2 = __floats2bfloat162_rn(rx, ry);
    hi = *(uint32_t*)&hp; lo = *(uint32_t*)&lp2;
}

#define LDSM4(r, a) \
    asm volatile("ldmatrix.sync.aligned.m8n8.x4.shared.b16 {%0,%1,%2,%3}, [%4];" \
        : "=r"((r)[0]), "=r"((r)[1]), "=r"((r)[2]), "=r"((r)[3]) : "r"(a))
#define LDSM4T(r, a) \
    asm volatile("ldmatrix.sync.aligned.m8n8.x4.trans.shared.b16 {%0,%1,%2,%3}, [%4];" \
        : "=r"((r)[0]), "=r"((r)[1]), "=r"((r)[2]), "=r"((r)[3]) : "r"(a))
#define MMA16816(d, a, b) \
    asm volatile("mma.sync.aligned.m16n8k16.row.col.f32.bf16.bf16.f32 " \
        "{%0,%1,%2,%3}, {%4,%5,%6,%7}, {%8,%9}, {%0,%1,%2,%3};" \
        : "+f"((d)[0]), "+f"((d)[1]), "+f"((d)[2]), "+f"((d)[3]) \
        : "r"((a)[0]), "r"((a)[1]), "r"((a)[2]), "r"((a)[3]), "r"((b)[0]), "r"((b)[1]))
#define CP_ASYNC16(dst, src) \
    asm volatile("cp.async.ca.shared.global [%0], [%1], 16;" :: "r"(dst), "l"(src))
#define CP_COMMIT() asm volatile("cp.async.commit_group;")
#define CP_WAIT(n)  asm volatile("cp.async.wait_group %0;" :: "n"(n))

// ---------------------------------------------------------------------------
// fp32 -> bf16 hi/lo split
// ---------------------------------------------------------------------------
__global__ __launch_bounds__(256)
void conv_split(const float* __restrict__ x, __nv_bfloat16* __restrict__ hi,
                __nv_bfloat16* __restrict__ lo)
{
    size_t i = ((size_t)blockIdx.x * 256 + threadIdx.x) * 4;
    float4 v = *(const float4*)&x[i];
    uint32_t h0, l0, h1, l1;
    split_pair(v.x, v.y, h0, l0);
    split_pair(v.z, v.w, h1, l1);
    *(uint2*)&hi[i] = make_uint2(h0, h1);
    *(uint2*)&lo[i] = make_uint2(l0, l1);
}

// ---------------------------------------------------------------------------
// Mask bit-pack
// ---------------------------------------------------------------------------
__global__ __launch_bounds__(256)
void pack_mask(const int* __restrict__ m)
{
    size_t i = (size_t)blockIdx.x * 256 + threadIdx.x;
    unsigned bit = (m[i] != 0) ? 1u : 0u;
    unsigned w = __ballot_sync(0xffffffff, bit);
    if ((threadIdx.x & 31) == 0) g_mbits[i >> 5] = w;
}

// ---------------------------------------------------------------------------
// bf16x3 HMMA GEMM, 3-stage cp.async pipeline, ONE sync per chunk.
// Block 128x128, K-chunk 16 (64 chunks), 256 threads = 8 warps (2m x 4n).
// ---------------------------------------------------------------------------
#define NST 3
#define NCHUNKS (DMODEL / 16)   // 64

__device__ __forceinline__ uint32_t tile_off(int s, int t, int row, int ch) {
    return (uint32_t)(((((s * 4 + t) * 128 + row) << 4) +
                       ((ch ^ ((row >> 2) & 1)) << 3)) << 1);
}

template<int LAYOUT>
__global__ __launch_bounds__(256)
void gemm_mma(const __nv_bfloat16* __restrict__ Ah, const __nv_bfloat16* __restrict__ Al,
              const __nv_bfloat16* __restrict__ Wh, const __nv_bfloat16* __restrict__ Wl,
              const float* __restrict__ bias, float* __restrict__ C,
              __nv_bfloat16* __restrict__ Chi, __nv_bfloat16* __restrict__ Clo,
              float scale)
{
    __shared__ __align__(16) __nv_bfloat16 sm[NST * 4 * 128 * 16];   // 49152 B

    const int tid  = threadIdx.x;
    const int lane = tid & 31;
    const int w    = tid >> 5;
    const int wm   = (w >> 2) * 64;
    const int wn   = (w & 3) * 32;
    const int n0 = blockIdx.x * 128;
    const int m0 = blockIdx.y * 128;
    const uint32_t sb = smem_u32(sm);

    const __nv_bfloat16* srcs[4] = {
        Ah + (size_t)m0 * DMODEL, Al + (size_t)m0 * DMODEL,
        Wh + (size_t)n0 * DMODEL, Wl + (size_t)n0 * DMODEL };

    const int lrow = tid >> 1;
    const int lch  = tid & 1;
    const size_t lgof = (size_t)lrow * DMODEL + lch * 8;

    float acc[4][4][4];
    #pragma unroll
    for (int mt = 0; mt < 4; mt++)
        #pragma unroll
        for (int nt = 0; nt < 4; nt++)
            #pragma unroll
            for (int e = 0; e < 4; e++) acc[mt][nt][e] = 0.f;

    #pragma unroll
    for (int c = 0; c < NST - 1; c++) {
        #pragma unroll
        for (int t = 0; t < 4; t++)
            CP_ASYNC16(sb + tile_off(c, t, lrow, lch), srcs[t] + lgof + c * 16);
        CP_COMMIT();
    }

    const int a_row = lane & 15;
    const int a_ch  = lane >> 4;

    for (int c = 0; c < NCHUNKS; c++) {
        const int s = c % NST;
        CP_WAIT(1);
        __syncthreads();

        // issue chunk c+2 NOW (stage (c+2)%NST was last read at chunk c-1;
        // the sync above proves all warps are past it), then compute chunk c.
        const int cn = c + NST - 1;
        if (cn < NCHUNKS) {
            #pragma unroll
            for (int t = 0; t < 4; t++)
                CP_ASYNC16(sb + tile_off(cn % NST, t, lrow, lch), srcs[t] + lgof + cn * 16);
        }
        CP_COMMIT();

        uint32_t ah[4][4], al[4][4];
        #pragma unroll
        for (int mt = 0; mt < 4; mt++) {
            LDSM4(ah[mt], sb + tile_off(s, 0, wm + mt * 16 + a_row, a_ch));
            LDSM4(al[mt], sb + tile_off(s, 1, wm + mt * 16 + a_row, a_ch));
        }
        uint32_t b4h[2][4], b4l[2][4];
        #pragma unroll
        for (int p = 0; p < 2; p++) {
            LDSM4(b4h[p], sb + tile_off(s, 2, wn + p * 16 + a_row, a_ch));
            LDSM4(b4l[p], sb + tile_off(s, 3, wn + p * 16 + a_row, a_ch));
        }
        uint32_t bh[4][2], bl[4][2];
        #pragma unroll
        for (int p = 0; p < 2; p++) {
            bh[2*p][0]   = b4h[p][0]; bh[2*p][1]   = b4h[p][2];
            bh[2*p+1][0] = b4h[p][1]; bh[2*p+1][1] = b4h[p][3];
            bl[2*p][0]   = b4l[p][0]; bl[2*p][1]   = b4l[p][2];
            bl[2*p+1][0] = b4l[p][1]; bl[2*p+1][1] = b4l[p][3];
        }
        #pragma unroll
        for (int mt = 0; mt < 4; mt++)
            #pragma unroll
            for (int nt = 0; nt < 4; nt++) {
                MMA16816(acc[mt][nt], ah[mt], bh[nt]);
                MMA16816(acc[mt][nt], ah[mt], bl[nt]);
                MMA16816(acc[mt][nt], al[mt], bh[nt]);
            }
    }

    const int er = lane >> 2;
    const int ec = (lane & 3) * 2;
    #pragma unroll
    for (int mt = 0; mt < 4; mt++) {
        #pragma unroll
        for (int half = 0; half < 2; half++) {
            int m = m0 + wm + mt * 16 + er + half * 8;
            #pragma unroll
            for (int nt = 0; nt < 4; nt++) {
                int n = n0 + wn + nt * 8 + ec;
                float f0 = (acc[mt][nt][half * 2 + 0] + __ldg(&bias[n]))     * scale;
                float f1 = (acc[mt][nt][half * 2 + 1] + __ldg(&bias[n + 1])) * scale;
                if (LAYOUT == 0) {
                    *(u64*)&C[(size_t)m * DMODEL + n] = pack2(f0, f1);
                } else {
                    int b  = m >> 11;
                    int sq = m & (SS - 1);
                    int hh = n >> 6;
                    int dk = n & (DK - 1);
                    size_t o = ((((size_t)b * H + hh) * SS + sq) * DK) + dk;
                    uint32_t hi, lo;
                    split_pair(f0, f1, hi, lo);
                    *(uint32_t*)&Chi[o] = hi;
                    *(uint32_t*)&Clo[o] = lo;
                }
            }
        }
    }
}

// ---------------------------------------------------------------------------
// HMMA flash attention (bf16x3), Q fragments in registers,
// 2-stage cp.async K/V pipeline, SW128-swizzled tiles (32 rows x 64 bf16).
// Block = 64 q-rows x one (b,h), 128 threads, 4 warps x 16q x 32keys.
// ---------------------------------------------------------------------------
// byte offset within sKV: stage s (0/1), tile t (Kh,Kl,Vh,Vl), row 0..31, 16B chunk 0..7
__device__ __forceinline__ uint32_t kv_off(int s, int t, int row, int ch) {
    return (uint32_t)((((s * 4 + t) * 32 + row) * 128) + ((ch ^ (row & 7)) * 16));
}

__global__ __launch_bounds__(128)
void attn_mma()
{
    __shared__ __align__(16) char sKV[32768];   // 2 stages x 4 tiles x 4KB

    const int tid  = threadIdx.x;
    const int lane = tid & 31;
    const int w    = tid >> 5;
    const int wq   = w * 16;
    const int q0 = blockIdx.x * 64;
    const int h  = blockIdx.y;
    const int bz = blockIdx.z;
    const uint32_t sb = smem_u32(sKV);

    const size_t hb = ((size_t)bz * H + h) * SS;
    const __nv_bfloat16* gqh = g_qh + (hb + q0) * DK;
    const __nv_bfloat16* gql = g_ql + (hb + q0) * DK;
    const __nv_bfloat16* kvsrc[4] = {
        g_kh + hb * DK, g_kl + hb * DK, g_vh + hb * DK, g_vl + hb * DK };

    // ---- stage Q (64x64 hi+lo) through stage-0 smem, swizzled ----
    #pragma unroll
    for (int i = 0; i < 8; i++) {
        int idx = tid + i * 128;            // 0..1023
        int arr = idx >> 9;                 // 0 = hi, 1 = lo
        int rem = idx & 511;
        int row = rem >> 3, ch = rem & 7;
        const __nv_bfloat16* src = (arr ? gql : gqh) + (size_t)row * DK + ch * 8;
        *(uint4*)(sKV + kv_off(0, arr * 2 + (row >> 5), row & 31, ch)) = *(const uint4*)src;
    }
    __syncthreads();

    // ---- extract Q fragments to registers (reused all 64 iterations) ----
    uint32_t qfh[4][4], qfl[4][4];
    {
        const int a_row = lane & 15, a_ch = lane >> 4;
        const int r = wq + a_row, lr = r & 31, ts = r >> 5;
        #pragma unroll
        for (int ks = 0; ks < 4; ks++) {
            LDSM4(qfh[ks], sb + kv_off(0, ts, lr, ks * 2 + a_ch));
            LDSM4(qfl[ks], sb + kv_off(0, 2 + ts, lr, ks * 2 + a_ch));
        }
    }
    __syncthreads();

    float acc[8][4];
    #pragma unroll
    for (int nt = 0; nt < 8; nt++)
        #pragma unroll
        for (int e = 0; e < 4; e++) acc[nt][e] = 0.f;
    float mrun0 = -1e30f, mrun1 = -1e30f;
    float lp0 = 0.f, lp1 = 0.f;

    const int er = lane >> 2, ec = (lane & 3) * 2;
    const size_t mrow0 = ((size_t)bz * SS + q0 + wq + er) * (SS / 32);
    const size_t mrow1 = mrow0 + 8 * (SS / 32);

    // ---- prologue: issue K/V tile 0 ----
    #pragma unroll
    for (int i = 0; i < 8; i++) {
        int idx = tid + i * 128;
        int t = idx >> 8, rem = idx & 255, row = rem >> 3, ch = rem & 7;
        CP_ASYNC16(sb + kv_off(0, t, row, ch), kvsrc[t] + (size_t)row * DK + ch * 8);
    }
    CP_COMMIT();

    for (int it = 0; it < SS / 32; it++) {
        const int st = it & 1;
        CP_WAIT(0);
        __syncthreads();

        if (it + 1 < SS / 32) {
            const int k0n = (it + 1) * 32;
            #pragma unroll
            for (int i = 0; i < 8; i++) {
                int idx = tid + i * 128;
                int t = idx >> 8, rem = idx & 255, row = rem >> 3, ch = rem & 7;
                CP_ASYNC16(sb + kv_off(st ^ 1, t, row, ch),
                           kvsrc[t] + (size_t)(k0n + row) * DK + ch * 8);
            }
        }
        CP_COMMIT();

        // --- scores: 16q x 32k per warp ---
        float sc[4][4];
        #pragma unroll
        for (int nt = 0; nt < 4; nt++)
            #pragma unroll
            for (int e = 0; e < 4; e++) sc[nt][e] = 0.f;

        #pragma unroll
        for (int ks = 0; ks < 4; ks++) {
            uint32_t kc0h[4], kc1h[4], kc0l[4], kc1l[4];
            LDSM4(kc0h, sb + kv_off(st, 0, lane, ks * 2));
            LDSM4(kc1h, sb + kv_off(st, 0, lane, ks * 2 + 1));
            LDSM4(kc0l, sb + kv_off(st, 1, lane, ks * 2));
            LDSM4(kc1l, sb + kv_off(st, 1, lane, ks * 2 + 1));
            #pragma unroll
            for (int nt = 0; nt < 4; nt++) {
                uint32_t bh[2] = { kc0h[nt], kc1h[nt] };
                uint32_t bl[2] = { kc0l[nt], kc1l[nt] };
                MMA16816(sc[nt], qfh[ks], bh);
                MMA16816(sc[nt], qfh[ks], bl);
                MMA16816(sc[nt], qfl[ks], bh);
            }
        }

        // --- mask + online softmax ---
        unsigned mw0 = g_mbits[mrow0 + it];
        unsigned mw1 = g_mbits[mrow1 + it];
        #pragma unroll
        for (int nt = 0; nt < 4; nt++) {
            int j0 = nt * 8 + ec;
            if (!((mw0 >> j0) & 1u))       sc[nt][0] = MASKVAL;
            if (!((mw0 >> (j0 + 1)) & 1u)) sc[nt][1] = MASKVAL;
            if (!((mw1 >> j0) & 1u))       sc[nt][2] = MASKVAL;
            if (!((mw1 >> (j0 + 1)) & 1u)) sc[nt][3] = MASKVAL;
        }
        float m0 = mrun0, m1 = mrun1;
        #pragma unroll
        for (int nt = 0; nt < 4; nt++) {
            m0 = fmaxf(m0, fmaxf(sc[nt][0], sc[nt][1]));
            m1 = fmaxf(m1, fmaxf(sc[nt][2], sc[nt][3]));
        }
        m0 = fmaxf(m0, __shfl_xor_sync(0xffffffff, m0, 1));
        m0 = fmaxf(m0, __shfl_xor_sync(0xffffffff, m0, 2));
        m1 = fmaxf(m1, __shfl_xor_sync(0xffffffff, m1, 1));
        m1 = fmaxf(m1, __shfl_xor_sync(0xffffffff, m1, 2));
        float al0 = ex2(mrun0 - m0);
        float al1 = ex2(mrun1 - m1);
        mrun0 = m0; mrun1 = m1;
        lp0 *= al0; lp1 *= al1;
        #pragma unroll
        for (int nt = 0; nt < 8; nt++) {
            acc[nt][0] *= al0; acc[nt][1] *= al0;
            acc[nt][2] *= al1; acc[nt][3] *= al1;
        }
        float s0 = 0.f, s1 = 0.f;
        #pragma unroll
        for (int nt = 0; nt < 4; nt++) {
            sc[nt][0] = ex2(sc[nt][0] - m0); s0 += sc[nt][0];
            sc[nt][1] = ex2(sc[nt][1] - m0); s0 += sc[nt][1];
            sc[nt][2] = ex2(sc[nt][2] - m1); s1 += sc[nt][2];
            sc[nt][3] = ex2(sc[nt][3] - m1); s1 += sc[nt][3];
        }
        lp0 += s0; lp1 += s1;

        // --- PV: P fragments from score registers, V via ldmatrix.x4.trans ---
        #pragma unroll
        for (int t2 = 0; t2 < 2; t2++) {
            uint32_t ph[4], pl[4];
            split_pair(sc[2*t2][0],   sc[2*t2][1],   ph[0], pl[0]);
            split_pair(sc[2*t2][2],   sc[2*t2][3],   ph[1], pl[1]);
            split_pair(sc[2*t2+1][0], sc[2*t2+1][1], ph[2], pl[2]);
            split_pair(sc[2*t2+1][2], sc[2*t2+1][3], ph[3], pl[3]);
            const int vrow = t2 * 16 + (lane & 15);
            const int vch  = lane >> 4;
            #pragma unroll
            for (int p = 0; p < 4; p++) {
                uint32_t v4h[4], v4l[4];
                LDSM4T(v4h, sb + kv_off(st, 2, vrow, 2 * p + vch));
                LDSM4T(v4l, sb + kv_off(st, 3, vrow, 2 * p + vch));
                uint32_t vh0[2] = { v4h[0], v4h[1] }, vl0[2] = { v4l[0], v4l[1] };
                uint32_t vh1[2] = { v4h[2], v4h[3] }, vl1[2] = { v4l[2], v4l[3] };
                MMA16816(acc[2*p],   ph, vh0);
                MMA16816(acc[2*p],   ph, vl0);
                MMA16816(acc[2*p],   pl, vh0);
                MMA16816(acc[2*p+1], ph, vh1);
                MMA16816(acc[2*p+1], ph, vl1);
                MMA16816(acc[2*p+1], pl, vh1);
            }
        }
    }

    // --- finalize ---
    lp0 += __shfl_xor_sync(0xffffffff, lp0, 1);
    lp0 += __shfl_xor_sync(0xffffffff, lp0, 2);
    lp1 += __shfl_xor_sync(0xffffffff, lp1, 1);
    lp1 += __shfl_xor_sync(0xffffffff, lp1, 2);
    float inv0 = 1.0f / lp0;
    float inv1 = 1.0f / lp1;

    size_t ro0 = ((size_t)bz * SS + q0 + wq + er) * DMODEL + (size_t)h * DK;
    size_t ro1 = ro0 + 8 * DMODEL;
    #pragma unroll
    for (int nt = 0; nt < 8; nt++) {
        int c = nt * 8 + ec;
        uint32_t hi, lo;
        split_pair(acc[nt][0] * inv0, acc[nt][1] * inv0, hi, lo);
        *(uint32_t*)&g_inh[ro0 + c] = hi;
        *(uint32_t*)&g_inl[ro0 + c] = lo;
        split_pair(acc[nt][2] * inv1, acc[nt][3] * inv1, hi, lo);
        *(uint32_t*)&g_inh[ro1 + c] = hi;
        *(uint32_t*)&g_inl[ro1 + c] = lo;
    }
}

// ---------------------------------------------------------------------------
extern "C" void kernel_launch(void* const* d_in, const int* in_sizes, int n_in,
                              void* d_out, int out_size)
{
    const float* q    = (const float*)d_in[0];
    const float* k    = (const float*)d_in[1];
    const float* v    = (const float*)d_in[2];
    const int*   mask = (const int*)  d_in[3];
    const float* Wq   = (const float*)d_in[4];
    const float* bq   = (const float*)d_in[5];
    const float* Wk   = (const float*)d_in[6];
    const float* bk   = (const float*)d_in[7];
    const float* Wv   = (const float*)d_in[8];
    const float* bv   = (const float*)d_in[9];
    const float* Wo   = (const float*)d_in[10];
    const float* bo   = (const float*)d_in[11];
    float* out = (float*)d_out;

    __nv_bfloat16 *ih, *il, *wh, *wl, *qh, *ql, *kh, *kl, *vh, *vl;
    cudaGetSymbolAddress((void**)&ih, g_inh);
    cudaGetSymbolAddress((void**)&il, g_inl);
    cudaGetSymbolAddress((void**)&wh, g_wh);
    cudaGetSymbolAddress((void**)&wl, g_wl);
    cudaGetSymbolAddress((void**)&qh, g_qh);
    cudaGetSymbolAddress((void**)&ql, g_ql);
    cudaGetSymbolAddress((void**)&kh, g_kh);
    cudaGetSymbolAddress((void**)&kl, g_kl);
    cudaGetSymbolAddress((void**)&vh, g_vh);
    cudaGetSymbolAddress((void**)&vl, g_vl);

    const int ACT_BLKS = (M_ROWS * DMODEL) / (256 * 4);   // 4096
    const int W_BLKS   = (DMODEL * DMODEL) / (256 * 4);   // 1024
    dim3 gg(DMODEL / 128, M_ROWS / 128);                   // (8, 32)

    pack_mask<<<(size_t)BB * SS * SS / 256, 256>>>(mask);

    conv_split<<<ACT_BLKS, 256>>>(q, ih, il);
    conv_split<<<W_BLKS, 256>>>(Wq, wh, wl);
    gemm_mma<1><<<gg, 256>>>(ih, il, wh, wl, bq, nullptr, qh, ql, QSCALE);

    conv_split<<<ACT_BLKS, 256>>>(k, ih, il);
    conv_split<<<W_BLKS, 256>>>(Wk, wh, wl);
    gemm_mma<1><<<gg, 256>>>(ih, il, wh, wl, bk, nullptr, kh, kl, 1.0f);

    conv_split<<<ACT_BLKS, 256>>>(v, ih, il);
    conv_split<<<W_BLKS, 256>>>(Wv, wh, wl);
    gemm_mma<1><<<gg, 256>>>(ih, il, wh, wl, bv, nullptr, vh, vl, 1.0f);

    attn_mma<<<dim3(SS / 64, H, BB), 128>>>();

    conv_split<<<W_BLKS, 256>>>(Wo, wh, wl);
    gemm_mma<0><<<gg, 256>>>(ih, il, wh, wl, bo, out, nullptr, nullptr, 1.0f);
}